// round 13
// baseline (speedup 1.0000x reference)
#include <cuda_runtime.h>
#include <cstdint>

#define D_MODEL 1024
#define NHEAD 16
#define DK 64
#define BATCH 4
#define SEQ 2048
#define ROWS (BATCH*SEQ)   // 8192

// Scratch (no allocations allowed)
__device__ float g_q[(size_t)ROWS * D_MODEL];
__device__ float g_k[(size_t)ROWS * D_MODEL];
__device__ float g_v[(size_t)ROWS * D_MODEL];
__device__ float g_ctx[(size_t)ROWS * D_MODEL];
__device__ float g_xr[(size_t)ROWS * D_MODEL];          // tf32-rounded x
__device__ float g_wr[(size_t)4 * D_MODEL * D_MODEL];   // tf32-rounded Wq,Wk,Wv,Wo

// ---------------------------------------------------------------------------
// Base-ISA helpers (sm_80 class only — NO tcgen05 on this toolchain target)
// ---------------------------------------------------------------------------
__device__ __forceinline__ uint32_t smem_u32(const void* p) {
    uint32_t a;
    asm("{ .reg .u64 t; cvta.to.shared.u64 t, %1; cvt.u32.u64 %0, t; }"
        : "=r"(a) : "l"(p));
    return a;
}
__device__ __forceinline__ uint32_t f2tf32(float x) {
    uint32_t u;
    asm("cvt.rna.tf32.f32 %0, %1;" : "=r"(u) : "f"(x));
    return u;
}
__device__ __forceinline__ float rnd_tf32(float x) {
    return __uint_as_float(f2tf32(x));
}
__device__ __forceinline__ void mma8(float* c, const uint32_t* a,
                                     uint32_t b0, uint32_t b1) {
    asm volatile(
        "mma.sync.aligned.m16n8k8.row.col.f32.tf32.tf32.f32 "
        "{%0,%1,%2,%3}, {%4,%5,%6,%7}, {%8,%9}, {%0,%1,%2,%3};"
        : "+f"(c[0]), "+f"(c[1]), "+f"(c[2]), "+f"(c[3])
        : "r"(a[0]), "r"(a[1]), "r"(a[2]), "r"(a[3]), "r"(b0), "r"(b1));
}
__device__ __forceinline__ void cp_async16(uint32_t dst, const void* src) {
    asm volatile("cp.async.cg.shared.global [%0], [%1], 16;"
                 :: "r"(dst), "l"(src));
}
#define CP_COMMIT() asm volatile("cp.async.commit_group;" ::: "memory")
#define CP_WAIT(n)  asm volatile("cp.async.wait_group %0;" :: "n"(n) : "memory")

// ---------------------------------------------------------------------------
// Pre-round: tf32(rna)-rounded copies (low 13 mantissa bits zero) so the mma
// stages consume raw fp32 bits as valid tf32 operands.
// ---------------------------------------------------------------------------
__global__ void pre_round_x(const float4* __restrict__ s, float4* __restrict__ d,
                            int n4) {
    int i = blockIdx.x * blockDim.x + threadIdx.x;
    if (i < n4) {
        float4 v = s[i];
        d[i] = make_float4(rnd_tf32(v.x), rnd_tf32(v.y),
                           rnd_tf32(v.z), rnd_tf32(v.w));
    }
}
__global__ void pre_round_w4(const float4* __restrict__ w0, const float4* __restrict__ w1,
                             const float4* __restrict__ w2, const float4* __restrict__ w3,
                             float4* __restrict__ d, int n4) {
    int i = blockIdx.x * blockDim.x + threadIdx.x;
    if (i >= n4) return;
    const float4* s = (blockIdx.y == 0) ? w0 : (blockIdx.y == 1) ? w1
                    : (blockIdx.y == 2) ? w2 : w3;
    float4 v = s[i];
    d[(size_t)blockIdx.y * n4 + i] = make_float4(rnd_tf32(v.x), rnd_tf32(v.y),
                                                 rnd_tf32(v.z), rnd_tf32(v.w));
}

// ---------------------------------------------------------------------------
// TF32 GEMM v4: C[m][n] = sum_k A[m][k] * W[n][k]  (x @ W^T)
// Pre-rounded inputs. CTA 128x128, 4 warps (64x64 each), k-chunk 32,
// 3-stage cp.async pipeline with ONE barrier per chunk:
//   CP_WAIT(1); sync; FILL(c+2); commit; compute(c)
// ---------------------------------------------------------------------------
#define LDA 36
#define TILEW (128*LDA)
#define BUFW  (2*TILEW)
#define NST 3
#define GEMM_SMEM (NST*BUFW*4)  // 110592 bytes

__global__ __launch_bounds__(128, 2) void gemm_tf32p(
    const float* __restrict__ A,
    const float* __restrict__ W0, const float* __restrict__ W1, const float* __restrict__ W2,
    float* __restrict__ C0, float* __restrict__ C1, float* __restrict__ C2,
    float q_scale, int round_out)
{
    extern __shared__ uint32_t sm[];
    const float* W;
    float* C;
    if (blockIdx.z == 0)      { W = W0; C = C0; }
    else if (blockIdx.z == 1) { W = W1; C = C1; }
    else                      { W = W2; C = C2; }
    const float scale = (blockIdx.z == 0) ? q_scale : 1.0f;

    const int tid = threadIdx.x;
    const int w = tid >> 5, l = tid & 31;
    const int g = l >> 2, t = l & 3;
    const int bm = blockIdx.y * 128;
    const int bn = blockIdx.x * 128;
    const int wm = (w & 1) * 64;
    const int wn = (w >> 1) * 64;
    const int rsub = l >> 3, c16 = l & 7;

    const float* Abase = A + (size_t)bm * D_MODEL;
    const float* Wbase = W + (size_t)bn * D_MODEL;
    const uint32_t smb = smem_u32(sm);

    auto FILL = [&](int chunk, int st) {
        uint32_t ab = smb + st * (BUFW * 4);
        uint32_t bb = ab + TILEW * 4;
#pragma unroll
        for (int it = 0; it < 8; it++) {
            int row = w * 32 + it * 4 + rsub;
            uint32_t doff = (uint32_t)(row * LDA + c16 * 4) * 4;
            size_t soff = (size_t)row * D_MODEL + chunk * 32 + c16 * 4;
            cp_async16(ab + doff, Abase + soff);
            cp_async16(bb + doff, Wbase + soff);
        }
    };

    float acc[4][8][4];
#pragma unroll
    for (int i = 0; i < 4; i++)
#pragma unroll
        for (int j = 0; j < 8; j++)
#pragma unroll
            for (int q = 0; q < 4; q++) acc[i][j][q] = 0.f;

    FILL(0, 0); CP_COMMIT();
    FILL(1, 1); CP_COMMIT();

    const int NCH = D_MODEL / 32;   // 32
    for (int c = 0; c < NCH; c++) {
        CP_WAIT(1);                 // this thread's chunk-c copies done
        __syncthreads();            // ...and everyone's (all waited pre-bar)
        if (c + 2 < NCH) FILL(c + 2, (c + 2) % NST);
        CP_COMMIT();                // always: keeps group<->chunk mapping
        const int st = c % NST;
        const uint32_t* Ab = sm + st * BUFW;
        const uint32_t* Bb = Ab + TILEW;
#pragma unroll
        for (int s8 = 0; s8 < 4; s8++) {
            uint32_t a[4][4];
#pragma unroll
            for (int i = 0; i < 4; i++) {
                const uint32_t* p = Ab + (wm + i * 16 + g) * LDA + s8 * 8 + t;
                a[i][0] = p[0];
                a[i][1] = p[8 * LDA];
                a[i][2] = p[4];
                a[i][3] = p[8 * LDA + 4];
            }
#pragma unroll
            for (int j = 0; j < 8; j++) {
                const uint32_t* p = Bb + (wn + j * 8 + g) * LDA + s8 * 8 + t;
                uint32_t b0 = p[0], b1 = p[4];
#pragma unroll
                for (int i = 0; i < 4; i++) mma8(acc[i][j], a[i], b0, b1);
            }
        }
    }

#pragma unroll
    for (int i = 0; i < 4; i++) {
        int r0 = bm + wm + i * 16 + g;
#pragma unroll
        for (int j = 0; j < 8; j++) {
            int col = bn + wn + j * 8 + 2 * t;
            float v0 = acc[i][j][0] * scale, v1 = acc[i][j][1] * scale;
            float v2 = acc[i][j][2] * scale, v3 = acc[i][j][3] * scale;
            if (round_out) {
                v0 = rnd_tf32(v0); v1 = rnd_tf32(v1);
                v2 = rnd_tf32(v2); v3 = rnd_tf32(v3);
            }
            *(float2*)(C + (size_t)r0 * D_MODEL + col) = make_float2(v0, v1);
            *(float2*)(C + (size_t)(r0 + 8) * D_MODEL + col) = make_float2(v2, v3);
        }
    }
}

// ---------------------------------------------------------------------------
// Fused causal attention v3. CTA = (b, h, 128 q rows), 256 threads / 8 warps,
// warp owns 16 score rows. Q fragments live in REGISTERS (staged once through
// the P buffer). K double-buffered via cp.async; V double-buffered via
// register-held transpose (loads issued at iter top, stored after PV).
// One __syncthreads per kt iteration.
// ---------------------------------------------------------------------------
#define AP 68
#define ATTN_SMEM ((128+128+128)*AP*4)   // P + K[2] + Vt[2] = 104448 bytes

__global__ __launch_bounds__(256) void attn_tc()
{
    extern __shared__ uint32_t sm[];
    uint32_t* Ps = sm;                 // [128][AP] (stages Q first)
    uint32_t* Kb = sm + 128 * AP;      // [2][64][AP]
    uint32_t* Vb = sm + 256 * AP;      // [2][64][AP] transposed [dd][n]

    const int tid = threadIdx.x;
    const int w = tid >> 5, l = tid & 31;
    const int g = l >> 2, t = l & 3;
    const int qt = blockIdx.x, h = blockIdx.y, b = blockIdx.z;

    const size_t base = (size_t)b * SEQ * D_MODEL + (size_t)h * DK;
    const float* qg = g_q + base + (size_t)qt * 128 * D_MODEL;
    const float* kg = g_k + base;
    const float* vg = g_v + base;
    const uint32_t smb = smem_u32(sm);
    const uint32_t Kb_b = smb + (uint32_t)128 * AP * 4;

    // Stage Q (pre-rounded, pre-scaled) into Ps
#pragma unroll
    for (int it = 0; it < 8; it++) {
        int flat = tid + it * 256;
        int m = flat >> 4, c4 = flat & 15;
        cp_async16(smb + (uint32_t)(m * AP + c4 * 4) * 4,
                   qg + (size_t)m * D_MODEL + c4 * 4);
    }
    CP_COMMIT();
    // K(0) -> buffer 0
#pragma unroll
    for (int it = 0; it < 4; it++) {
        int flat = tid + it * 256;
        int n = flat >> 4, c4 = flat & 15;
        cp_async16(Kb_b + (uint32_t)(n * AP + c4 * 4) * 4,
                   kg + (size_t)n * D_MODEL + c4 * 4);
    }
    CP_COMMIT();
    CP_WAIT(1);          // Q landed (K0 may still be in flight)
    __syncthreads();

    // Q fragments -> registers (32 regs)
    const int rowA = w * 16 + g, rowB = rowA + 8;
    uint32_t qf[8][4];
#pragma unroll
    for (int kc = 0; kc < 8; kc++) {
        const uint32_t* pa = Ps + rowA * AP + kc * 8 + t;
        const uint32_t* pb = Ps + rowB * AP + kc * 8 + t;
        qf[kc][0] = pa[0]; qf[kc][1] = pb[0];
        qf[kc][2] = pa[4]; qf[kc][3] = pb[4];
    }

    // V(0) transpose -> Vb[0] (4x4 register blocks)
    const int dd4 = tid & 15, ng = tid >> 4;
    {
        float4 r[4];
#pragma unroll
        for (int i = 0; i < 4; i++)
            r[i] = *(const float4*)(vg + (size_t)(ng * 4 + i) * D_MODEL + dd4 * 4);
        float* rf = (float*)r;
#pragma unroll
        for (int u = 0; u < 4; u++)
            *(uint4*)(Vb + (dd4 * 4 + u) * AP + ng * 4) = make_uint4(
                __float_as_uint(rf[0 * 4 + u]), __float_as_uint(rf[1 * 4 + u]),
                __float_as_uint(rf[2 * 4 + u]), __float_as_uint(rf[3 * 4 + u]));
    }

    float mr2[2] = {-1e30f, -1e30f};
    float lr2[2] = {0.f, 0.f};
    float acco[8][4];
#pragma unroll
    for (int j = 0; j < 8; j++)
#pragma unroll
        for (int q = 0; q < 4; q++) acco[j][q] = 0.f;

    const int KT = 2 * qt + 1;
    for (int kt = 0; kt <= KT; kt++) {
        const int cur = kt & 1, nxt = cur ^ 1;
        const bool more = (kt < KT);
        float4 vs[4];
        if (more) {
            // prefetch K(kt+1) via cp.async and V(kt+1) into registers
            const float* kg_t = kg + (size_t)(kt + 1) * 64 * D_MODEL;
#pragma unroll
            for (int it = 0; it < 4; it++) {
                int flat = tid + it * 256;
                int n = flat >> 4, c4 = flat & 15;
                cp_async16(Kb_b + (uint32_t)(nxt * 64 * AP + n * AP + c4 * 4) * 4,
                           kg_t + (size_t)n * D_MODEL + c4 * 4);
            }
            const float* vg_t = vg + (size_t)(kt + 1) * 64 * D_MODEL;
#pragma unroll
            for (int i = 0; i < 4; i++)
                vs[i] = *(const float4*)(vg_t + (size_t)(ng * 4 + i) * D_MODEL + dd4 * 4);
        }
        CP_COMMIT();
        CP_WAIT(1);          // K(kt) complete (this thread)
        __syncthreads();     // ...globally; V(kt) stores from last iter visible

        // ---- S = Q K^T : 16x64 per warp ----
        const uint32_t* kfb = Kb + cur * 64 * AP + g * AP + t;
        float accs[8][4];
#pragma unroll
        for (int j = 0; j < 8; j++)
#pragma unroll
            for (int q = 0; q < 4; q++) accs[j][q] = 0.f;
#pragma unroll
        for (int kc = 0; kc < 8; kc++) {
#pragma unroll
            for (int j = 0; j < 8; j++) {
                const uint32_t* bp = kfb + (j * 8) * AP + kc * 8;
                mma8(accs[j], qf[kc], bp[0], bp[4]);
            }
        }

        // ---- causal mask ----
        const int off = qt * 128 - kt * 64;
        if (off < 64) {
#pragma unroll
            for (int j = 0; j < 8; j++) {
                int c0 = j * 8 + 2 * t;
                if (c0 > off + rowA)     accs[j][0] = -1e30f;
                if (c0 + 1 > off + rowA) accs[j][1] = -1e30f;
                if (c0 > off + rowB)     accs[j][2] = -1e30f;
                if (c0 + 1 > off + rowB) accs[j][3] = -1e30f;
            }
        }

        // ---- online softmax (rows A and B; quad shuffles) ----
        float mxA = -1e30f, mxB = -1e30f;
#pragma unroll
        for (int j = 0; j < 8; j++) {
            mxA = fmaxf(mxA, fmaxf(accs[j][0], accs[j][1]));
            mxB = fmaxf(mxB, fmaxf(accs[j][2], accs[j][3]));
        }
        mxA = fmaxf(mxA, __shfl_xor_sync(0xffffffffu, mxA, 1));
        mxA = fmaxf(mxA, __shfl_xor_sync(0xffffffffu, mxA, 2));
        mxB = fmaxf(mxB, __shfl_xor_sync(0xffffffffu, mxB, 1));
        mxB = fmaxf(mxB, __shfl_xor_sync(0xffffffffu, mxB, 2));

        float mnA = fmaxf(mr2[0], mxA), mnB = fmaxf(mr2[1], mxB);
        float alA = __expf(mr2[0] - mnA), alB = __expf(mr2[1] - mnB);
        mr2[0] = mnA; mr2[1] = mnB;

        float sA = 0.f, sB = 0.f;
#pragma unroll
        for (int j = 0; j < 8; j++) {
            accs[j][0] = __expf(accs[j][0] - mnA);
            accs[j][1] = __expf(accs[j][1] - mnA);
            accs[j][2] = __expf(accs[j][2] - mnB);
            accs[j][3] = __expf(accs[j][3] - mnB);
            sA += accs[j][0] + accs[j][1];
            sB += accs[j][2] + accs[j][3];
        }
        sA += __shfl_xor_sync(0xffffffffu, sA, 1);
        sA += __shfl_xor_sync(0xffffffffu, sA, 2);
        sB += __shfl_xor_sync(0xffffffffu, sB, 1);
        sB += __shfl_xor_sync(0xffffffffu, sB, 2);
        lr2[0] = lr2[0] * alA + sA;
        lr2[1] = lr2[1] * alB + sB;

#pragma unroll
        for (int j = 0; j < 8; j++) {
            acco[j][0] *= alA; acco[j][1] *= alA;
            acco[j][2] *= alB; acco[j][3] *= alB;
        }

        // ---- store P rows (own warp only) as tf32 ----
        uint32_t* psA = Ps + rowA * AP;
        uint32_t* psB = Ps + rowB * AP;
#pragma unroll
        for (int j = 0; j < 8; j++) {
            *(uint2*)(psA + j * 8 + 2 * t) =
                make_uint2(f2tf32(accs[j][0]), f2tf32(accs[j][1]));
            *(uint2*)(psB + j * 8 + 2 * t) =
                make_uint2(f2tf32(accs[j][2]), f2tf32(accs[j][3]));
        }
        __syncwarp();

        // ---- O += P V ----
        const uint32_t* vfb = Vb + cur * 64 * AP + g * AP + t;
        const uint32_t* pA = psA + t;
        const uint32_t* pB = psB + t;
#pragma unroll
        for (int kc = 0; kc < 8; kc++) {
            uint32_t a[4];
            a[0] = pA[kc * 8];     a[1] = pB[kc * 8];
            a[2] = pA[kc * 8 + 4]; a[3] = pB[kc * 8 + 4];
#pragma unroll
            for (int j = 0; j < 8; j++) {
                const uint32_t* bp = vfb + (j * 8) * AP + kc * 8;
                mma8(acco[j], a, bp[0], bp[4]);
            }
        }

        // ---- deferred V(kt+1) transpose store into the other buffer ----
        if (more) {
            float* rf = (float*)vs;
#pragma unroll
            for (int u = 0; u < 4; u++)
                *(uint4*)(Vb + nxt * 64 * AP + (dd4 * 4 + u) * AP + ng * 4) =
                    make_uint4(__float_as_uint(rf[0 * 4 + u]),
                               __float_as_uint(rf[1 * 4 + u]),
                               __float_as_uint(rf[2 * 4 + u]),
                               __float_as_uint(rf[3 * 4 + u]));
        }
        __syncwarp();   // own-warp P reads done before next-iter stores
    }

    // Epilogue: normalize, tf32-round (feeds O-projection), write ctx
    float invA = 1.f / lr2[0], invB = 1.f / lr2[1];
    float* og = g_ctx + base;
    size_t rA = (size_t)(qt * 128 + rowA) * D_MODEL;
    size_t rB = (size_t)(qt * 128 + rowB) * D_MODEL;
#pragma unroll
    for (int j = 0; j < 8; j++) {
        int col = j * 8 + 2 * t;
        *(float2*)(og + rA + col) = make_float2(
            rnd_tf32(acco[j][0] * invA), rnd_tf32(acco[j][1] * invA));
        *(float2*)(og + rB + col) = make_float2(
            rnd_tf32(acco[j][2] * invB), rnd_tf32(acco[j][3] * invB));
    }
}

// ---------------------------------------------------------------------------
// Launch
// ---------------------------------------------------------------------------
extern "C" void kernel_launch(void* const* d_in, const int* in_sizes, int n_in,
                              void* d_out, int out_size)
{
    (void)in_sizes; (void)n_in; (void)out_size;
    const float* x  = (const float*)d_in[0];
    const float* Wq = (const float*)d_in[1];
    const float* Wk = (const float*)d_in[2];
    const float* Wv = (const float*)d_in[3];
    const float* Wo = (const float*)d_in[4];
    float* out = (float*)d_out;

    float *qp, *kp, *vp, *cp, *xr, *wr;
    cudaGetSymbolAddress((void**)&qp, g_q);
    cudaGetSymbolAddress((void**)&kp, g_k);
    cudaGetSymbolAddress((void**)&vp, g_v);
    cudaGetSymbolAddress((void**)&cp, g_ctx);
    cudaGetSymbolAddress((void**)&xr, g_xr);
    cudaGetSymbolAddress((void**)&wr, g_wr);

    cudaFuncSetAttribute(gemm_tf32p, cudaFuncAttributeMaxDynamicSharedMemorySize,
                         GEMM_SMEM);
    cudaFuncSetAttribute(attn_tc, cudaFuncAttributeMaxDynamicSharedMemorySize,
                         ATTN_SMEM);

    const int NX4 = ROWS * D_MODEL / 4;
    const int NW4 = D_MODEL * D_MODEL / 4;
    const size_t WSZ = (size_t)D_MODEL * D_MODEL;
    pre_round_x<<<(NX4 + 255) / 256, 256>>>((const float4*)x, (float4*)xr, NX4);
    dim3 gw((NW4 + 255) / 256, 4);
    pre_round_w4<<<gw, 256>>>((const float4*)Wq, (const float4*)Wk,
                              (const float4*)Wv, (const float4*)Wo,
                              (float4*)wr, NW4);

    // QKV projections (Q rows pre-scaled by 1/sqrt(dk), outputs tf32-rounded)
    dim3 gproj(D_MODEL / 128, ROWS / 128, 3);
    gemm_tf32p<<<gproj, 128, GEMM_SMEM>>>(xr, wr + 0 * WSZ, wr + 1 * WSZ, wr + 2 * WSZ,
                                          qp, kp, vp, 0.125f, 1);

    // Causal attention
    dim3 gattn(SEQ / 128, NHEAD, BATCH);
    attn_tc<<<gattn, 256, ATTN_SMEM>>>();

    // Output projection (fp32 output)
    dim3 gout(D_MODEL / 128, ROWS / 128, 1);
    gemm_tf32p<<<gout, 128, GEMM_SMEM>>>(cp, wr + 3 * WSZ, wr + 3 * WSZ, wr + 3 * WSZ,
                                         out, out, out, 1.0f, 0);
}

// round 14
// speedup vs baseline: 1.0357x; 1.0357x over previous
#include <cuda_runtime.h>
#include <cstdint>

#define D_MODEL 1024
#define NHEAD 16
#define DK 64
#define BATCH 4
#define SEQ 2048
#define ROWS (BATCH*SEQ)   // 8192

// Scratch (no allocations allowed)
__device__ float g_q[(size_t)ROWS * D_MODEL];
__device__ float g_k[(size_t)ROWS * D_MODEL];
__device__ float g_v[(size_t)ROWS * D_MODEL];
__device__ float g_ctx[(size_t)ROWS * D_MODEL];
__device__ float g_xr[(size_t)ROWS * D_MODEL];          // tf32-rounded x
__device__ float g_wr[(size_t)4 * D_MODEL * D_MODEL];   // tf32-rounded Wq,Wk,Wv,Wo

// ---------------------------------------------------------------------------
// Base-ISA helpers (sm_80 class only — NO tcgen05 on this toolchain target)
// ---------------------------------------------------------------------------
__device__ __forceinline__ uint32_t smem_u32(const void* p) {
    uint32_t a;
    asm("{ .reg .u64 t; cvta.to.shared.u64 t, %1; cvt.u32.u64 %0, t; }"
        : "=r"(a) : "l"(p));
    return a;
}
__device__ __forceinline__ uint32_t f2tf32(float x) {
    uint32_t u;
    asm("cvt.rna.tf32.f32 %0, %1;" : "=r"(u) : "f"(x));
    return u;
}
__device__ __forceinline__ float rnd_tf32(float x) {
    return __uint_as_float(f2tf32(x));
}
__device__ __forceinline__ void mma8(float* c, const uint32_t* a,
                                     uint32_t b0, uint32_t b1) {
    asm volatile(
        "mma.sync.aligned.m16n8k8.row.col.f32.tf32.tf32.f32 "
        "{%0,%1,%2,%3}, {%4,%5,%6,%7}, {%8,%9}, {%0,%1,%2,%3};"
        : "+f"(c[0]), "+f"(c[1]), "+f"(c[2]), "+f"(c[3])
        : "r"(a[0]), "r"(a[1]), "r"(a[2]), "r"(a[3]), "r"(b0), "r"(b1));
}
__device__ __forceinline__ void cp_async16(uint32_t dst, const void* src) {
    asm volatile("cp.async.cg.shared.global [%0], [%1], 16;"
                 :: "r"(dst), "l"(src));
}
#define CP_COMMIT() asm volatile("cp.async.commit_group;" ::: "memory")
#define CP_WAIT(n)  asm volatile("cp.async.wait_group %0;" :: "n"(n) : "memory")

// ---------------------------------------------------------------------------
// Pre-round: tf32(rna)-rounded copies.
// ---------------------------------------------------------------------------
__global__ void pre_round_x(const float4* __restrict__ s, float4* __restrict__ d,
                            int n4) {
    int i = blockIdx.x * blockDim.x + threadIdx.x;
    if (i < n4) {
        float4 v = s[i];
        d[i] = make_float4(rnd_tf32(v.x), rnd_tf32(v.y),
                           rnd_tf32(v.z), rnd_tf32(v.w));
    }
}
__global__ void pre_round_w4(const float4* __restrict__ w0, const float4* __restrict__ w1,
                             const float4* __restrict__ w2, const float4* __restrict__ w3,
                             float4* __restrict__ d, int n4) {
    int i = blockIdx.x * blockDim.x + threadIdx.x;
    if (i >= n4) return;
    const float4* s = (blockIdx.y == 0) ? w0 : (blockIdx.y == 1) ? w1
                    : (blockIdx.y == 2) ? w2 : w3;
    float4 v = s[i];
    d[(size_t)blockIdx.y * n4 + i] = make_float4(rnd_tf32(v.x), rnd_tf32(v.y),
                                                 rnd_tf32(v.z), rnd_tf32(v.w));
}

// ---------------------------------------------------------------------------
// TF32 GEMM v5: C[m][n] = sum_k A[m][k] * W[n][k]  (x @ W^T)
// CTA 128x128, 4 warps (64x64), k-chunk 32. NST=2 (smem 72KB) so 3 CTAs/SM
// (occupancy was the round-13 limiter). One barrier per chunk:
//   CP_WAIT(0); sync; FILL(c+1,other); commit; compute(c)
// ---------------------------------------------------------------------------
#define LDA 36
#define TILEW (128*LDA)
#define BUFW  (2*TILEW)
#define NST 2
#define GEMM_SMEM (NST*BUFW*4)  // 73728 bytes

__global__ __launch_bounds__(128, 3) void gemm_tf32p(
    const float* __restrict__ A,
    const float* __restrict__ W0, const float* __restrict__ W1, const float* __restrict__ W2,
    float* __restrict__ C0, float* __restrict__ C1, float* __restrict__ C2,
    float q_scale, int round_out)
{
    extern __shared__ uint32_t sm[];
    const float* W;
    float* C;
    if (blockIdx.z == 0)      { W = W0; C = C0; }
    else if (blockIdx.z == 1) { W = W1; C = C1; }
    else                      { W = W2; C = C2; }
    const float scale = (blockIdx.z == 0) ? q_scale : 1.0f;

    const int tid = threadIdx.x;
    const int w = tid >> 5, l = tid & 31;
    const int g = l >> 2, t = l & 3;
    const int bm = blockIdx.y * 128;
    const int bn = blockIdx.x * 128;
    const int wm = (w & 1) * 64;
    const int wn = (w >> 1) * 64;
    const int rsub = l >> 3, c16 = l & 7;

    const float* Abase = A + (size_t)bm * D_MODEL;
    const float* Wbase = W + (size_t)bn * D_MODEL;
    const uint32_t smb = smem_u32(sm);

    auto FILL = [&](int chunk, int st) {
        uint32_t ab = smb + st * (BUFW * 4);
        uint32_t bb = ab + TILEW * 4;
#pragma unroll
        for (int it = 0; it < 8; it++) {
            int row = w * 32 + it * 4 + rsub;
            uint32_t doff = (uint32_t)(row * LDA + c16 * 4) * 4;
            size_t soff = (size_t)row * D_MODEL + chunk * 32 + c16 * 4;
            cp_async16(ab + doff, Abase + soff);
            cp_async16(bb + doff, Wbase + soff);
        }
    };

    float acc[4][8][4];
#pragma unroll
    for (int i = 0; i < 4; i++)
#pragma unroll
        for (int j = 0; j < 8; j++)
#pragma unroll
            for (int q = 0; q < 4; q++) acc[i][j][q] = 0.f;

    FILL(0, 0); CP_COMMIT();

    const int NCH = D_MODEL / 32;   // 32
    for (int c = 0; c < NCH; c++) {
        CP_WAIT(0);                 // chunk c (issued last iter) complete
        __syncthreads();            // globally visible
        if (c + 1 < NCH) FILL(c + 1, (c + 1) & 1);
        CP_COMMIT();
        const int st = c & 1;
        const uint32_t* Ab = sm + st * BUFW;
        const uint32_t* Bb = Ab + TILEW;
#pragma unroll
        for (int s8 = 0; s8 < 4; s8++) {
            uint32_t a[4][4];
#pragma unroll
            for (int i = 0; i < 4; i++) {
                const uint32_t* p = Ab + (wm + i * 16 + g) * LDA + s8 * 8 + t;
                a[i][0] = p[0];
                a[i][1] = p[8 * LDA];
                a[i][2] = p[4];
                a[i][3] = p[8 * LDA + 4];
            }
#pragma unroll
            for (int j = 0; j < 8; j++) {
                const uint32_t* p = Bb + (wn + j * 8 + g) * LDA + s8 * 8 + t;
                uint32_t b0 = p[0], b1 = p[4];
#pragma unroll
                for (int i = 0; i < 4; i++) mma8(acc[i][j], a[i], b0, b1);
            }
        }
        __syncthreads();            // done reading stage st before refill
    }

#pragma unroll
    for (int i = 0; i < 4; i++) {
        int r0 = bm + wm + i * 16 + g;
#pragma unroll
        for (int j = 0; j < 8; j++) {
            int col = bn + wn + j * 8 + 2 * t;
            float v0 = acc[i][j][0] * scale, v1 = acc[i][j][1] * scale;
            float v2 = acc[i][j][2] * scale, v3 = acc[i][j][3] * scale;
            if (round_out) {
                v0 = rnd_tf32(v0); v1 = rnd_tf32(v1);
                v2 = rnd_tf32(v2); v3 = rnd_tf32(v3);
            }
            *(float2*)(C + (size_t)r0 * D_MODEL + col) = make_float2(v0, v1);
            *(float2*)(C + (size_t)(r0 + 8) * D_MODEL + col) = make_float2(v2, v3);
        }
    }
}

// ---------------------------------------------------------------------------
// Fused causal attention v4. CTA = (b, h, 64 q rows), 128 threads / 4 warps,
// warp owns 16 rows. Q fragments in registers. K double-buffered (cp.async),
// V single-buffered with register-held prefetch (store after a barrier).
// Smem 69632 B -> 3 CTAs/SM (the round-13 occupancy fix).
// ---------------------------------------------------------------------------
#define AP 68
#define ATTN_SMEM ((64+128+64)*AP*4)   // P + K[2] + V = 69632 bytes

__global__ __launch_bounds__(128, 3) void attn_tc()
{
    extern __shared__ uint32_t sm[];
    uint32_t* Ps = sm;                 // [64][AP] (stages Q first)
    uint32_t* Kb = sm + 64 * AP;       // [2][64][AP]
    uint32_t* Vt = sm + 192 * AP;      // [64][AP] transposed [dd][n]

    const int tid = threadIdx.x;
    const int w = tid >> 5, l = tid & 31;
    const int g = l >> 2, t = l & 3;
    const int qt = blockIdx.x, h = blockIdx.y, b = blockIdx.z;

    const size_t base = (size_t)b * SEQ * D_MODEL + (size_t)h * DK;
    const float* qg = g_q + base + (size_t)qt * 64 * D_MODEL;
    const float* kg = g_k + base;
    const float* vg = g_v + base;
    const uint32_t smb = smem_u32(sm);
    const uint32_t Kb_b = smb + (uint32_t)64 * AP * 4;

    // Stage Q (pre-rounded, pre-scaled) into Ps: 64 rows x 16 float4
#pragma unroll
    for (int it = 0; it < 8; it++) {
        int flat = tid + it * 128;
        int m = flat >> 4, c4 = flat & 15;
        cp_async16(smb + (uint32_t)(m * AP + c4 * 4) * 4,
                   qg + (size_t)m * D_MODEL + c4 * 4);
    }
    CP_COMMIT();
    // K(0) -> buffer 0
#pragma unroll
    for (int it = 0; it < 8; it++) {
        int flat = tid + it * 128;
        int n = flat >> 4, c4 = flat & 15;
        cp_async16(Kb_b + (uint32_t)(n * AP + c4 * 4) * 4,
                   kg + (size_t)n * D_MODEL + c4 * 4);
    }
    CP_COMMIT();
    CP_WAIT(1);          // Q landed
    __syncthreads();

    // Q fragments -> registers (32 regs)
    const int rowA = w * 16 + g, rowB = rowA + 8;
    uint32_t qf[8][4];
#pragma unroll
    for (int kc = 0; kc < 8; kc++) {
        const uint32_t* pa = Ps + rowA * AP + kc * 8 + t;
        const uint32_t* pb = Ps + rowB * AP + kc * 8 + t;
        qf[kc][0] = pa[0]; qf[kc][1] = pb[0];
        qf[kc][2] = pa[4]; qf[kc][3] = pb[4];
    }

    // V(0) transpose -> Vt (each thread: two 4x4 blocks)
#pragma unroll
    for (int it = 0; it < 2; it++) {
        int bidx = tid + it * 128;
        int dd4 = bidx & 15, ng = bidx >> 4;
        float4 r[4];
#pragma unroll
        for (int i = 0; i < 4; i++)
            r[i] = *(const float4*)(vg + (size_t)(ng * 4 + i) * D_MODEL + dd4 * 4);
        float* rf = (float*)r;
#pragma unroll
        for (int u = 0; u < 4; u++)
            *(uint4*)(Vt + (dd4 * 4 + u) * AP + ng * 4) = make_uint4(
                __float_as_uint(rf[0 * 4 + u]), __float_as_uint(rf[1 * 4 + u]),
                __float_as_uint(rf[2 * 4 + u]), __float_as_uint(rf[3 * 4 + u]));
    }

    float mr2[2] = {-1e30f, -1e30f};
    float lr2[2] = {0.f, 0.f};
    float acco[8][4];
#pragma unroll
    for (int j = 0; j < 8; j++)
#pragma unroll
        for (int q = 0; q < 4; q++) acco[j][q] = 0.f;

    const int KT = qt;
    for (int kt = 0; kt <= KT; kt++) {
        const int cur = kt & 1, nxt = cur ^ 1;
        const bool more = (kt < KT);
        float4 vs[2][4];
        if (more) {
            // prefetch K(kt+1) via cp.async; V(kt+1) into registers
            const float* kg_t = kg + (size_t)(kt + 1) * 64 * D_MODEL;
#pragma unroll
            for (int it = 0; it < 8; it++) {
                int flat = tid + it * 128;
                int n = flat >> 4, c4 = flat & 15;
                cp_async16(Kb_b + (uint32_t)(nxt * 64 * AP + n * AP + c4 * 4) * 4,
                           kg_t + (size_t)n * D_MODEL + c4 * 4);
            }
            const float* vg_t = vg + (size_t)(kt + 1) * 64 * D_MODEL;
#pragma unroll
            for (int it = 0; it < 2; it++) {
                int bidx = tid + it * 128;
                int dd4 = bidx & 15, ng = bidx >> 4;
#pragma unroll
                for (int i = 0; i < 4; i++)
                    vs[it][i] = *(const float4*)(vg_t + (size_t)(ng * 4 + i) * D_MODEL + dd4 * 4);
            }
        }
        CP_COMMIT();
        CP_WAIT(1);          // K(kt) complete (this thread)
        __syncthreads();     // ...globally; V(kt) stores visible

        // ---- S = Q K^T : 16x64 per warp ----
        const uint32_t* kfb = Kb + cur * 64 * AP + g * AP + t;
        float accs[8][4];
#pragma unroll
        for (int j = 0; j < 8; j++)
#pragma unroll
            for (int q = 0; q < 4; q++) accs[j][q] = 0.f;
#pragma unroll
        for (int kc = 0; kc < 8; kc++) {
#pragma unroll
            for (int j = 0; j < 8; j++) {
                const uint32_t* bp = kfb + (j * 8) * AP + kc * 8;
                mma8(accs[j], qf[kc], bp[0], bp[4]);
            }
        }

        // ---- causal mask (diagonal tile only) ----
        if (kt == KT) {
#pragma unroll
            for (int j = 0; j < 8; j++) {
                int c0 = j * 8 + 2 * t;
                if (c0 > rowA)     accs[j][0] = -1e30f;
                if (c0 + 1 > rowA) accs[j][1] = -1e30f;
                if (c0 > rowB)     accs[j][2] = -1e30f;
                if (c0 + 1 > rowB) accs[j][3] = -1e30f;
            }
        }

        // ---- online softmax ----
        float mxA = -1e30f, mxB = -1e30f;
#pragma unroll
        for (int j = 0; j < 8; j++) {
            mxA = fmaxf(mxA, fmaxf(accs[j][0], accs[j][1]));
            mxB = fmaxf(mxB, fmaxf(accs[j][2], accs[j][3]));
        }
        mxA = fmaxf(mxA, __shfl_xor_sync(0xffffffffu, mxA, 1));
        mxA = fmaxf(mxA, __shfl_xor_sync(0xffffffffu, mxA, 2));
        mxB = fmaxf(mxB, __shfl_xor_sync(0xffffffffu, mxB, 1));
        mxB = fmaxf(mxB, __shfl_xor_sync(0xffffffffu, mxB, 2));

        float mnA = fmaxf(mr2[0], mxA), mnB = fmaxf(mr2[1], mxB);
        float alA = __expf(mr2[0] - mnA), alB = __expf(mr2[1] - mnB);
        mr2[0] = mnA; mr2[1] = mnB;

        float sA = 0.f, sB = 0.f;
#pragma unroll
        for (int j = 0; j < 8; j++) {
            accs[j][0] = __expf(accs[j][0] - mnA);
            accs[j][1] = __expf(accs[j][1] - mnA);
            accs[j][2] = __expf(accs[j][2] - mnB);
            accs[j][3] = __expf(accs[j][3] - mnB);
            sA += accs[j][0] + accs[j][1];
            sB += accs[j][2] + accs[j][3];
        }
        sA += __shfl_xor_sync(0xffffffffu, sA, 1);
        sA += __shfl_xor_sync(0xffffffffu, sA, 2);
        sB += __shfl_xor_sync(0xffffffffu, sB, 1);
        sB += __shfl_xor_sync(0xffffffffu, sB, 2);
        lr2[0] = lr2[0] * alA + sA;
        lr2[1] = lr2[1] * alB + sB;

#pragma unroll
        for (int j = 0; j < 8; j++) {
            acco[j][0] *= alA; acco[j][1] *= alA;
            acco[j][2] *= alB; acco[j][3] *= alB;
        }

        // ---- store P rows (own warp only) as tf32 ----
        uint32_t* psA = Ps + rowA * AP;
        uint32_t* psB = Ps + rowB * AP;
#pragma unroll
        for (int j = 0; j < 8; j++) {
            *(uint2*)(psA + j * 8 + 2 * t) =
                make_uint2(f2tf32(accs[j][0]), f2tf32(accs[j][1]));
            *(uint2*)(psB + j * 8 + 2 * t) =
                make_uint2(f2tf32(accs[j][2]), f2tf32(accs[j][3]));
        }
        __syncwarp();

        // ---- O += P V ----
        const uint32_t* vfb = Vt + g * AP + t;
        const uint32_t* pA = psA + t;
        const uint32_t* pB = psB + t;
#pragma unroll
        for (int kc = 0; kc < 8; kc++) {
            uint32_t a[4];
            a[0] = pA[kc * 8];     a[1] = pB[kc * 8];
            a[2] = pA[kc * 8 + 4]; a[3] = pB[kc * 8 + 4];
#pragma unroll
            for (int j = 0; j < 8; j++) {
                const uint32_t* bp = vfb + (j * 8) * AP + kc * 8;
                mma8(acco[j], a, bp[0], bp[4]);
            }
        }

        if (more) {
            __syncthreads();   // all warps done reading V(kt)
            // deferred V(kt+1) transpose store (single buffer)
#pragma unroll
            for (int it = 0; it < 2; it++) {
                int bidx = tid + it * 128;
                int dd4 = bidx & 15, ng = bidx >> 4;
                float* rf = (float*)vs[it];
#pragma unroll
                for (int u = 0; u < 4; u++)
                    *(uint4*)(Vt + (dd4 * 4 + u) * AP + ng * 4) = make_uint4(
                        __float_as_uint(rf[0 * 4 + u]), __float_as_uint(rf[1 * 4 + u]),
                        __float_as_uint(rf[2 * 4 + u]), __float_as_uint(rf[3 * 4 + u]));
            }
        }
        __syncwarp();
    }

    // Epilogue: normalize, tf32-round (feeds O-projection), write ctx
    float invA = 1.f / lr2[0], invB = 1.f / lr2[1];
    float* og = g_ctx + base;
    size_t rA = (size_t)(qt * 64 + rowA) * D_MODEL;
    size_t rB = (size_t)(qt * 64 + rowB) * D_MODEL;
#pragma unroll
    for (int j = 0; j < 8; j++) {
        int col = j * 8 + 2 * t;
        *(float2*)(og + rA + col) = make_float2(
            rnd_tf32(acco[j][0] * invA), rnd_tf32(acco[j][1] * invA));
        *(float2*)(og + rB + col) = make_float2(
            rnd_tf32(acco[j][2] * invB), rnd_tf32(acco[j][3] * invB));
    }
}

// ---------------------------------------------------------------------------
// Launch
// ---------------------------------------------------------------------------
extern "C" void kernel_launch(void* const* d_in, const int* in_sizes, int n_in,
                              void* d_out, int out_size)
{
    (void)in_sizes; (void)n_in; (void)out_size;
    const float* x  = (const float*)d_in[0];
    const float* Wq = (const float*)d_in[1];
    const float* Wk = (const float*)d_in[2];
    const float* Wv = (const float*)d_in[3];
    const float* Wo = (const float*)d_in[4];
    float* out = (float*)d_out;

    float *qp, *kp, *vp, *cp, *xr, *wr;
    cudaGetSymbolAddress((void**)&qp, g_q);
    cudaGetSymbolAddress((void**)&kp, g_k);
    cudaGetSymbolAddress((void**)&vp, g_v);
    cudaGetSymbolAddress((void**)&cp, g_ctx);
    cudaGetSymbolAddress((void**)&xr, g_xr);
    cudaGetSymbolAddress((void**)&wr, g_wr);

    cudaFuncSetAttribute(gemm_tf32p, cudaFuncAttributeMaxDynamicSharedMemorySize,
                         GEMM_SMEM);
    cudaFuncSetAttribute(attn_tc, cudaFuncAttributeMaxDynamicSharedMemorySize,
                         ATTN_SMEM);

    const int NX4 = ROWS * D_MODEL / 4;
    const int NW4 = D_MODEL * D_MODEL / 4;
    const size_t WSZ = (size_t)D_MODEL * D_MODEL;
    pre_round_x<<<(NX4 + 255) / 256, 256>>>((const float4*)x, (float4*)xr, NX4);
    dim3 gw((NW4 + 255) / 256, 4);
    pre_round_w4<<<gw, 256>>>((const float4*)Wq, (const float4*)Wk,
                              (const float4*)Wv, (const float4*)Wo,
                              (float4*)wr, NW4);

    // QKV projections (Q rows pre-scaled by 1/sqrt(dk), outputs tf32-rounded)
    dim3 gproj(D_MODEL / 128, ROWS / 128, 3);
    gemm_tf32p<<<gproj, 128, GEMM_SMEM>>>(xr, wr + 0 * WSZ, wr + 1 * WSZ, wr + 2 * WSZ,
                                          qp, kp, vp, 0.125f, 1);

    // Causal attention (64-row q tiles, 3 CTAs/SM)
    dim3 gattn(SEQ / 64, NHEAD, BATCH);
    attn_tc<<<gattn, 128, ATTN_SMEM>>>();

    // Output projection (fp32 output)
    dim3 gout(D_MODEL / 128, ROWS / 128, 1);
    gemm_tf32p<<<gout, 128, GEMM_SMEM>>>(cp, wr + 3 * WSZ, wr + 3 * WSZ, wr + 3 * WSZ,
                                         out, out, out, 1.0f, 0);
}

// round 15
// speedup vs baseline: 1.3576x; 1.3109x over previous
#include <cuda_runtime.h>
#include <cuda_fp16.h>
#include <cstdint>

#define D_MODEL 1024
#define NHEAD 16
#define DK 64
#define BATCH 4
#define SEQ 2048
#define ROWS (BATCH*SEQ)   // 8192
#define DW (D_MODEL/2)     // 512 words (half2) per row

// Scratch (no allocations allowed). q/k/v/ctx/x/W stored as packed half2 words.
__device__ uint32_t g_q[(size_t)ROWS * DW];
__device__ uint32_t g_k[(size_t)ROWS * DW];
__device__ uint32_t g_v[(size_t)ROWS * DW];
__device__ uint32_t g_ctx[(size_t)ROWS * DW];
__device__ uint32_t g_xh[(size_t)ROWS * DW];
__device__ uint32_t g_wh[(size_t)4 * D_MODEL * DW];

// ---------------------------------------------------------------------------
// Base-ISA helpers (sm_80 class only — NO tcgen05 on this toolchain target)
// ---------------------------------------------------------------------------
__device__ __forceinline__ uint32_t smem_u32(const void* p) {
    uint32_t a;
    asm("{ .reg .u64 t; cvta.to.shared.u64 t, %1; cvt.u32.u64 %0, t; }"
        : "=r"(a) : "l"(p));
    return a;
}
__device__ __forceinline__ uint32_t packh2(float a, float b) {
    __half2 h = __floats2half2_rn(a, b);
    return *(uint32_t*)&h;
}
// fp16 m16n8k16, fp32 accumulate: same fragment register shape as tf32 k8.
__device__ __forceinline__ void mma16(float* c, const uint32_t* a,
                                      uint32_t b0, uint32_t b1) {
    asm volatile(
        "mma.sync.aligned.m16n8k16.row.col.f32.f16.f16.f32 "
        "{%0,%1,%2,%3}, {%4,%5,%6,%7}, {%8,%9}, {%0,%1,%2,%3};"
        : "+f"(c[0]), "+f"(c[1]), "+f"(c[2]), "+f"(c[3])
        : "r"(a[0]), "r"(a[1]), "r"(a[2]), "r"(a[3]), "r"(b0), "r"(b1));
}
__device__ __forceinline__ void cp_async16(uint32_t dst, const void* src) {
    asm volatile("cp.async.cg.shared.global [%0], [%1], 16;"
                 :: "r"(dst), "l"(src));
}
#define CP_COMMIT() asm volatile("cp.async.commit_group;" ::: "memory")
#define CP_WAIT(n)  asm volatile("cp.async.wait_group %0;" :: "n"(n) : "memory")

// ---------------------------------------------------------------------------
// Pre-convert fp32 -> packed fp16 (rn). Thread handles 8 floats -> uint4.
// ---------------------------------------------------------------------------
__global__ void pre_half_x(const float4* __restrict__ s, uint4* __restrict__ d,
                           int n8) {
    int i = blockIdx.x * blockDim.x + threadIdx.x;
    if (i < n8) {
        float4 v0 = s[2 * i], v1 = s[2 * i + 1];
        d[i] = make_uint4(packh2(v0.x, v0.y), packh2(v0.z, v0.w),
                          packh2(v1.x, v1.y), packh2(v1.z, v1.w));
    }
}
__global__ void pre_half_w4(const float4* __restrict__ w0, const float4* __restrict__ w1,
                            const float4* __restrict__ w2, const float4* __restrict__ w3,
                            uint4* __restrict__ d, int n8) {
    int i = blockIdx.x * blockDim.x + threadIdx.x;
    if (i >= n8) return;
    const float4* s = (blockIdx.y == 0) ? w0 : (blockIdx.y == 1) ? w1
                    : (blockIdx.y == 2) ? w2 : w3;
    float4 v0 = s[2 * i], v1 = s[2 * i + 1];
    d[(size_t)blockIdx.y * n8 + i] =
        make_uint4(packh2(v0.x, v0.y), packh2(v0.z, v0.w),
                   packh2(v1.x, v1.y), packh2(v1.z, v1.w));
}

// ---------------------------------------------------------------------------
// FP16 GEMM: C[m][n] = sum_k A[m][k] * W[n][k]  (x @ W^T), A/W packed half2.
// CTA 128x128, 4 warps (64x64), k-chunk 64 (32 words/row), NST=2,
// 3-launch cp.async pipeline identical in structure to the r14 tf32 kernel.
// round_half=1 -> write packed half2 to Ch (with scale); else float to Cf.
// ---------------------------------------------------------------------------
#define LDAW 36
#define TILEW (128*LDAW)
#define BUFW  (2*TILEW)
#define NST 2
#define GEMM_SMEM (NST*BUFW*4)  // 73728 bytes

__global__ __launch_bounds__(128, 3) void gemm_fp16(
    const uint32_t* __restrict__ A,
    const uint32_t* __restrict__ W0, const uint32_t* __restrict__ W1,
    const uint32_t* __restrict__ W2,
    float* __restrict__ Cf,
    uint32_t* __restrict__ H0, uint32_t* __restrict__ H1, uint32_t* __restrict__ H2,
    float q_scale, int round_half)
{
    extern __shared__ uint32_t sm[];
    const uint32_t* W;
    uint32_t* Ch;
    if (blockIdx.z == 0)      { W = W0; Ch = H0; }
    else if (blockIdx.z == 1) { W = W1; Ch = H1; }
    else                      { W = W2; Ch = H2; }
    const float scale = (blockIdx.z == 0) ? q_scale : 1.0f;

    const int tid = threadIdx.x;
    const int w = tid >> 5, l = tid & 31;
    const int g = l >> 2, t = l & 3;
    const int bm = blockIdx.y * 128;
    const int bn = blockIdx.x * 128;
    const int wm = (w & 1) * 64;
    const int wn = (w >> 1) * 64;

    const uint32_t* Abase = A + (size_t)bm * DW;
    const uint32_t* Wbase = W + (size_t)bn * DW;
    const uint32_t smb = smem_u32(sm);

    const int fr = tid >> 1;             // fill row (0..63), +64 for second
    const int fc = (tid & 1) * 4;        // starting 4-word unit

    auto FILL = [&](int chunk, int st) {
        uint32_t ab = smb + st * (BUFW * 4);
        uint32_t bb = ab + TILEW * 4;
#pragma unroll
        for (int i = 0; i < 4; i++) {
            int c4 = (fc + i) * 4;                   // word offset in row
#pragma unroll
            for (int rh = 0; rh < 2; rh++) {
                int row = fr + rh * 64;
                uint32_t doff = (uint32_t)(row * LDAW + c4) * 4;
                size_t soff = (size_t)row * DW + chunk * 32 + c4;
                cp_async16(ab + doff, Abase + soff);
                cp_async16(bb + doff, Wbase + soff);
            }
        }
    };

    float acc[4][8][4];
#pragma unroll
    for (int i = 0; i < 4; i++)
#pragma unroll
        for (int j = 0; j < 8; j++)
#pragma unroll
            for (int q = 0; q < 4; q++) acc[i][j][q] = 0.f;

    FILL(0, 0); CP_COMMIT();

    const int NCH = D_MODEL / 64;   // 16 chunks of k=64 (32 words)
    for (int c = 0; c < NCH; c++) {
        CP_WAIT(0);
        __syncthreads();
        if (c + 1 < NCH) FILL(c + 1, (c + 1) & 1);
        CP_COMMIT();
        const int st = c & 1;
        const uint32_t* Ab = sm + st * BUFW;
        const uint32_t* Bb = Ab + TILEW;
#pragma unroll
        for (int s = 0; s < 4; s++) {            // 4 k16-steps per chunk
            uint32_t a[4][4];
#pragma unroll
            for (int i = 0; i < 4; i++) {
                const uint32_t* p = Ab + (wm + i * 16 + g) * LDAW + s * 8 + t;
                a[i][0] = p[0];
                a[i][1] = p[8 * LDAW];
                a[i][2] = p[4];
                a[i][3] = p[8 * LDAW + 4];
            }
#pragma unroll
            for (int j = 0; j < 8; j++) {
                const uint32_t* p = Bb + (wn + j * 8 + g) * LDAW + s * 8 + t;
                uint32_t b0 = p[0], b1 = p[4];
#pragma unroll
                for (int i = 0; i < 4; i++) mma16(acc[i][j], a[i], b0, b1);
            }
        }
        __syncthreads();
    }

#pragma unroll
    for (int i = 0; i < 4; i++) {
        int r0 = bm + wm + i * 16 + g;
#pragma unroll
        for (int j = 0; j < 8; j++) {
            float v0 = acc[i][j][0] * scale, v1 = acc[i][j][1] * scale;
            float v2 = acc[i][j][2] * scale, v3 = acc[i][j][3] * scale;
            if (round_half) {
                int wcol = ((bn + wn + j * 8) >> 1) + t;
                Ch[(size_t)r0 * DW + wcol] = packh2(v0, v1);
                Ch[(size_t)(r0 + 8) * DW + wcol] = packh2(v2, v3);
            } else {
                int col = bn + wn + j * 8 + 2 * t;
                *(float2*)(Cf + (size_t)r0 * D_MODEL + col) = make_float2(v0, v1);
                *(float2*)(Cf + (size_t)(r0 + 8) * D_MODEL + col) = make_float2(v2, v3);
            }
        }
    }
}

// ---------------------------------------------------------------------------
// Fused causal attention, fp16 mma (m16n8k16, fp32 softmax/accum).
// CTA = (b, h, 64 q rows), 128 thr / 4 warps, warp owns 16 rows; Q frags in
// registers; K double-buffered (cp.async); V single-buffered, register-held
// transposed prefetch. Structure identical to r14; half-width rows.
// ---------------------------------------------------------------------------
#define APW 36
#define ATTN_SMEM ((64+128+64)*APW*4)   // P + K[2] + Vt = 36864 bytes

__global__ __launch_bounds__(128, 3) void attn_fp16()
{
    extern __shared__ uint32_t sm[];
    uint32_t* Ps = sm;                 // [64][APW] (stages Q first)
    uint32_t* Kb = sm + 64 * APW;      // [2][64][APW]
    uint32_t* Vt = sm + 192 * APW;     // [64][APW] transposed [dd][n-pairs]

    const int tid = threadIdx.x;
    const int w = tid >> 5, l = tid & 31;
    const int g = l >> 2, t = l & 3;
    const int qt = blockIdx.x, h = blockIdx.y, b = blockIdx.z;

    const size_t base = (size_t)b * SEQ * DW + (size_t)h * (DK / 2);
    const uint32_t* qg = g_q + base + (size_t)qt * 64 * DW;
    const uint32_t* kg = g_k + base;
    const uint32_t* vg = g_v + base;
    const uint32_t smb = smem_u32(sm);
    const uint32_t Kb_b = smb + (uint32_t)64 * APW * 4;

    const int fr = tid >> 1;             // 0..63
    const int fc = (tid & 1) * 4;

    // Stage Q into Ps (rows of 32 words)
#pragma unroll
    for (int i = 0; i < 4; i++) {
        int c4 = (fc + i) * 4;
        cp_async16(smb + (uint32_t)(fr * APW + c4) * 4, qg + (size_t)fr * DW + c4);
    }
    CP_COMMIT();
    // K(0) -> buffer 0
#pragma unroll
    for (int i = 0; i < 4; i++) {
        int c4 = (fc + i) * 4;
        cp_async16(Kb_b + (uint32_t)(fr * APW + c4) * 4, kg + (size_t)fr * DW + c4);
    }
    CP_COMMIT();
    CP_WAIT(1);          // Q landed
    __syncthreads();

    // Q fragments -> registers (16 regs; k64 = 4 k16-steps)
    const int rowA = w * 16 + g, rowB = rowA + 8;
    uint32_t qf[4][4];
#pragma unroll
    for (int s = 0; s < 4; s++) {
        const uint32_t* pa = Ps + rowA * APW + s * 8 + t;
        const uint32_t* pb = Ps + rowB * APW + s * 8 + t;
        qf[s][0] = pa[0]; qf[s][1] = pb[0];
        qf[s][2] = pa[4]; qf[s][3] = pb[4];
    }

    // V(0) transpose -> Vt. Warp w handles dd rows [w*16, w*16+16); lane np
    // loads seq rows 2np,2np+1, words w*8..w*8+7 -> 2x2 half-transpose packs.
    const int np = l;
    const uint32_t* vr0 = vg + (size_t)(2 * np) * DW + w * 8;
    {
        uint4 a0 = *(const uint4*)vr0;
        uint4 a1 = *(const uint4*)(vr0 + 4);
        uint4 b0 = *(const uint4*)(vr0 + DW);
        uint4 b1 = *(const uint4*)(vr0 + DW + 4);
        const uint32_t* aw = (const uint32_t*)&a0;   // a0,a1 contiguous? no —
        uint32_t av[8] = {a0.x, a0.y, a0.z, a0.w, a1.x, a1.y, a1.z, a1.w};
        uint32_t bv[8] = {b0.x, b0.y, b0.z, b0.w, b1.x, b1.y, b1.z, b1.w};
        (void)aw;
#pragma unroll
        for (int w8 = 0; w8 < 8; w8++) {
            int dd = w * 16 + 2 * w8;
            Vt[dd * APW + np]       = __byte_perm(av[w8], bv[w8], 0x5410);
            Vt[(dd + 1) * APW + np] = __byte_perm(av[w8], bv[w8], 0x7632);
        }
    }

    float mr2[2] = {-1e30f, -1e30f};
    float lr2[2] = {0.f, 0.f};
    float acco[8][4];
#pragma unroll
    for (int j = 0; j < 8; j++)
#pragma unroll
        for (int q = 0; q < 4; q++) acco[j][q] = 0.f;

    const int KT = qt;
    for (int kt = 0; kt <= KT; kt++) {
        const int cur = kt & 1, nxt = cur ^ 1;
        const bool more = (kt < KT);
        uint32_t av[8], bv[8];
        if (more) {
            const uint32_t* kg_t = kg + (size_t)(kt + 1) * 64 * DW;
#pragma unroll
            for (int i = 0; i < 4; i++) {
                int c4 = (fc + i) * 4;
                cp_async16(Kb_b + (uint32_t)(nxt * 64 * APW + fr * APW + c4) * 4,
                           kg_t + (size_t)fr * DW + c4);
            }
            const uint32_t* vp = vg + (size_t)(kt + 1) * 64 * DW +
                                 (size_t)(2 * np) * DW + w * 8;
            uint4 x0 = *(const uint4*)vp;
            uint4 x1 = *(const uint4*)(vp + 4);
            uint4 y0 = *(const uint4*)(vp + DW);
            uint4 y1 = *(const uint4*)(vp + DW + 4);
            av[0] = x0.x; av[1] = x0.y; av[2] = x0.z; av[3] = x0.w;
            av[4] = x1.x; av[5] = x1.y; av[6] = x1.z; av[7] = x1.w;
            bv[0] = y0.x; bv[1] = y0.y; bv[2] = y0.z; bv[3] = y0.w;
            bv[4] = y1.x; bv[5] = y1.y; bv[6] = y1.z; bv[7] = y1.w;
        }
        CP_COMMIT();
        CP_WAIT(1);          // K(kt) complete
        __syncthreads();     // globally; V(kt) stores visible

        // ---- S = Q K^T : 16x64 per warp, 4 k16-steps ----
        const uint32_t* kfb = Kb + cur * 64 * APW + g * APW + t;
        float accs[8][4];
#pragma unroll
        for (int j = 0; j < 8; j++)
#pragma unroll
            for (int q = 0; q < 4; q++) accs[j][q] = 0.f;
#pragma unroll
        for (int s = 0; s < 4; s++) {
#pragma unroll
            for (int j = 0; j < 8; j++) {
                const uint32_t* bp = kfb + (j * 8) * APW + s * 8;
                mma16(accs[j], qf[s], bp[0], bp[4]);
            }
        }

        // ---- causal mask (diagonal tile only) ----
        if (kt == KT) {
#pragma unroll
            for (int j = 0; j < 8; j++) {
                int c0 = j * 8 + 2 * t;
                if (c0 > rowA)     accs[j][0] = -1e30f;
                if (c0 + 1 > rowA) accs[j][1] = -1e30f;
                if (c0 > rowB)     accs[j][2] = -1e30f;
                if (c0 + 1 > rowB) accs[j][3] = -1e30f;
            }
        }

        // ---- online softmax (fp32) ----
        float mxA = -1e30f, mxB = -1e30f;
#pragma unroll
        for (int j = 0; j < 8; j++) {
            mxA = fmaxf(mxA, fmaxf(accs[j][0], accs[j][1]));
            mxB = fmaxf(mxB, fmaxf(accs[j][2], accs[j][3]));
        }
        mxA = fmaxf(mxA, __shfl_xor_sync(0xffffffffu, mxA, 1));
        mxA = fmaxf(mxA, __shfl_xor_sync(0xffffffffu, mxA, 2));
        mxB = fmaxf(mxB, __shfl_xor_sync(0xffffffffu, mxB, 1));
        mxB = fmaxf(mxB, __shfl_xor_sync(0xffffffffu, mxB, 2));

        float mnA = fmaxf(mr2[0], mxA), mnB = fmaxf(mr2[1], mxB);
        float alA = __expf(mr2[0] - mnA), alB = __expf(mr2[1] - mnB);
        mr2[0] = mnA; mr2[1] = mnB;

        float sA = 0.f, sB = 0.f;
#pragma unroll
        for (int j = 0; j < 8; j++) {
            accs[j][0] = __expf(accs[j][0] - mnA);
            accs[j][1] = __expf(accs[j][1] - mnA);
            accs[j][2] = __expf(accs[j][2] - mnB);
            accs[j][3] = __expf(accs[j][3] - mnB);
            sA += accs[j][0] + accs[j][1];
            sB += accs[j][2] + accs[j][3];
        }
        sA += __shfl_xor_sync(0xffffffffu, sA, 1);
        sA += __shfl_xor_sync(0xffffffffu, sA, 2);
        sB += __shfl_xor_sync(0xffffffffu, sB, 1);
        sB += __shfl_xor_sync(0xffffffffu, sB, 2);
        lr2[0] = lr2[0] * alA + sA;
        lr2[1] = lr2[1] * alB + sB;

#pragma unroll
        for (int j = 0; j < 8; j++) {
            acco[j][0] *= alA; acco[j][1] *= alA;
            acco[j][2] *= alB; acco[j][3] *= alB;
        }

        // ---- store P rows (own warp only) as packed half2 ----
        uint32_t* psA = Ps + rowA * APW;
        uint32_t* psB = Ps + rowB * APW;
#pragma unroll
        for (int j = 0; j < 8; j++) {
            psA[j * 4 + t] = packh2(accs[j][0], accs[j][1]);
            psB[j * 4 + t] = packh2(accs[j][2], accs[j][3]);
        }
        __syncwarp();

        // ---- O += P V : 4 k16-steps ----
        const uint32_t* vfb = Vt + g * APW + t;
        const uint32_t* pA = Ps + rowA * APW + t;
        const uint32_t* pB = Ps + rowB * APW + t;
#pragma unroll
        for (int s = 0; s < 4; s++) {
            uint32_t a[4];
            a[0] = pA[s * 8];     a[1] = pB[s * 8];
            a[2] = pA[s * 8 + 4]; a[3] = pB[s * 8 + 4];
#pragma unroll
            for (int j = 0; j < 8; j++) {
                const uint32_t* bp = vfb + (j * 8) * APW + s * 8;
                mma16(acco[j], a, bp[0], bp[4]);
            }
        }

        if (more) {
            __syncthreads();   // all warps done reading V(kt)
#pragma unroll
            for (int w8 = 0; w8 < 8; w8++) {
                int dd = w * 16 + 2 * w8;
                Vt[dd * APW + np]       = __byte_perm(av[w8], bv[w8], 0x5410);
                Vt[(dd + 1) * APW + np] = __byte_perm(av[w8], bv[w8], 0x7632);
            }
        }
        __syncwarp();
    }

    // Epilogue: normalize, write ctx as packed half2
    float invA = 1.f / lr2[0], invB = 1.f / lr2[1];
    uint32_t* og = g_ctx + base;
    size_t rA = (size_t)(qt * 64 + rowA) * DW;
    size_t rB = (size_t)(qt * 64 + rowB) * DW;
#pragma unroll
    for (int j = 0; j < 8; j++) {
        og[rA + j * 4 + t] = packh2(acco[j][0] * invA, acco[j][1] * invA);
        og[rB + j * 4 + t] = packh2(acco[j][2] * invB, acco[j][3] * invB);
    }
}

// ---------------------------------------------------------------------------
// Launch
// ---------------------------------------------------------------------------
extern "C" void kernel_launch(void* const* d_in, const int* in_sizes, int n_in,
                              void* d_out, int out_size)
{
    (void)in_sizes; (void)n_in; (void)out_size;
    const float* x  = (const float*)d_in[0];
    const float* Wq = (const float*)d_in[1];
    const float* Wk = (const float*)d_in[2];
    const float* Wv = (const float*)d_in[3];
    const float* Wo = (const float*)d_in[4];
    float* out = (float*)d_out;

    uint32_t *qp, *kp, *vp, *cp, *xh, *wh;
    cudaGetSymbolAddress((void**)&qp, g_q);
    cudaGetSymbolAddress((void**)&kp, g_k);
    cudaGetSymbolAddress((void**)&vp, g_v);
    cudaGetSymbolAddress((void**)&cp, g_ctx);
    cudaGetSymbolAddress((void**)&xh, g_xh);
    cudaGetSymbolAddress((void**)&wh, g_wh);

    cudaFuncSetAttribute(gemm_fp16, cudaFuncAttributeMaxDynamicSharedMemorySize,
                         GEMM_SMEM);
    cudaFuncSetAttribute(attn_fp16, cudaFuncAttributeMaxDynamicSharedMemorySize,
                         ATTN_SMEM);

    const int NX8 = ROWS * D_MODEL / 8;
    const int NW8 = D_MODEL * D_MODEL / 8;
    const size_t WSZW = (size_t)D_MODEL * DW;
    pre_half_x<<<(NX8 + 255) / 256, 256>>>((const float4*)x, (uint4*)xh, NX8);
    dim3 gw((NW8 + 255) / 256, 4);
    pre_half_w4<<<gw, 256>>>((const float4*)Wq, (const float4*)Wk,
                             (const float4*)Wv, (const float4*)Wo,
                             (uint4*)wh, NW8);

    // QKV projections (Q pre-scaled by 1/sqrt(dk); outputs packed half2)
    dim3 gproj(D_MODEL / 128, ROWS / 128, 3);
    gemm_fp16<<<gproj, 128, GEMM_SMEM>>>(xh, wh, wh + WSZW, wh + 2 * WSZW,
                                         nullptr, qp, kp, vp, 0.125f, 1);

    // Causal attention (fp16 mma)
    dim3 gattn(SEQ / 64, NHEAD, BATCH);
    attn_fp16<<<gattn, 128, ATTN_SMEM>>>();

    // Output projection (fp32 output)
    dim3 gout(D_MODEL / 128, ROWS / 128, 1);
    gemm_fp16<<<gout, 128, GEMM_SMEM>>>(cp, wh + 3 * WSZW, wh + 3 * WSZW,
                                        wh + 3 * WSZW,
                                        out, nullptr, nullptr, nullptr, 1.0f, 0);
}

// round 16
// speedup vs baseline: 1.4070x; 1.0364x over previous
#include <cuda_runtime.h>
#include <cuda_fp16.h>
#include <cstdint>

#define D_MODEL 1024
#define NHEAD 16
#define DK 64
#define BATCH 4
#define SEQ 2048
#define ROWS (BATCH*SEQ)   // 8192
#define DW (D_MODEL/2)     // 512 words (half2) per row

// Scratch (no allocations allowed). q/k/v/ctx/x/W stored as packed half2 words.
__device__ uint32_t g_q[(size_t)ROWS * DW];
__device__ uint32_t g_k[(size_t)ROWS * DW];
__device__ uint32_t g_v[(size_t)ROWS * DW];
__device__ uint32_t g_ctx[(size_t)ROWS * DW];
__device__ uint32_t g_xh[(size_t)ROWS * DW];
__device__ uint32_t g_wh[(size_t)4 * D_MODEL * DW];

// ---------------------------------------------------------------------------
// Base-ISA helpers (sm_80 class only — NO tcgen05 on this toolchain target)
// ---------------------------------------------------------------------------
__device__ __forceinline__ uint32_t smem_u32(const void* p) {
    uint32_t a;
    asm("{ .reg .u64 t; cvta.to.shared.u64 t, %1; cvt.u32.u64 %0, t; }"
        : "=r"(a) : "l"(p));
    return a;
}
__device__ __forceinline__ uint32_t packh2(float a, float b) {
    __half2 h = __floats2half2_rn(a, b);
    return *(uint32_t*)&h;
}
// Two exps in one MUFU op: 2^x on packed fp16 pair.
__device__ __forceinline__ uint32_t h2ex2(uint32_t x) {
    uint32_t y;
    asm("ex2.approx.f16x2 %0, %1;" : "=r"(y) : "r"(x));
    return y;
}
__device__ __forceinline__ float ex2f(float x) {
    float y;
    asm("ex2.approx.f32 %0, %1;" : "=f"(y) : "f"(x));
    return y;
}
// fp16 m16n8k16, fp32 accumulate.
__device__ __forceinline__ void mma16(float* c, const uint32_t* a,
                                      uint32_t b0, uint32_t b1) {
    asm volatile(
        "mma.sync.aligned.m16n8k16.row.col.f32.f16.f16.f32 "
        "{%0,%1,%2,%3}, {%4,%5,%6,%7}, {%8,%9}, {%0,%1,%2,%3};"
        : "+f"(c[0]), "+f"(c[1]), "+f"(c[2]), "+f"(c[3])
        : "r"(a[0]), "r"(a[1]), "r"(a[2]), "r"(a[3]), "r"(b0), "r"(b1));
}
__device__ __forceinline__ void cp_async16(uint32_t dst, const void* src) {
    asm volatile("cp.async.cg.shared.global [%0], [%1], 16;"
                 :: "r"(dst), "l"(src));
}
#define CP_COMMIT() asm volatile("cp.async.commit_group;" ::: "memory")
#define CP_WAIT(n)  asm volatile("cp.async.wait_group %0;" :: "n"(n) : "memory")

// ---------------------------------------------------------------------------
// Pre-convert fp32 -> packed fp16 (rn). Thread handles 8 floats -> uint4.
// ---------------------------------------------------------------------------
__global__ void pre_half_x(const float4* __restrict__ s, uint4* __restrict__ d,
                           int n8) {
    int i = blockIdx.x * blockDim.x + threadIdx.x;
    if (i < n8) {
        float4 v0 = s[2 * i], v1 = s[2 * i + 1];
        d[i] = make_uint4(packh2(v0.x, v0.y), packh2(v0.z, v0.w),
                          packh2(v1.x, v1.y), packh2(v1.z, v1.w));
    }
}
__global__ void pre_half_w4(const float4* __restrict__ w0, const float4* __restrict__ w1,
                            const float4* __restrict__ w2, const float4* __restrict__ w3,
                            uint4* __restrict__ d, int n8) {
    int i = blockIdx.x * blockDim.x + threadIdx.x;
    if (i >= n8) return;
    const float4* s = (blockIdx.y == 0) ? w0 : (blockIdx.y == 1) ? w1
                    : (blockIdx.y == 2) ? w2 : w3;
    float4 v0 = s[2 * i], v1 = s[2 * i + 1];
    d[(size_t)blockIdx.y * n8 + i] =
        make_uint4(packh2(v0.x, v0.y), packh2(v0.z, v0.w),
                   packh2(v1.x, v1.y), packh2(v1.z, v1.w));
}

// ---------------------------------------------------------------------------
// FP16 GEMM (unchanged from round 15): C[m][n] = sum_k A[m][k] * W[n][k]
// ---------------------------------------------------------------------------
#define LDAW 36
#define TILEW (128*LDAW)
#define BUFW  (2*TILEW)
#define NST 2
#define GEMM_SMEM (NST*BUFW*4)  // 73728 bytes

__global__ __launch_bounds__(128, 3) void gemm_fp16(
    const uint32_t* __restrict__ A,
    const uint32_t* __restrict__ W0, const uint32_t* __restrict__ W1,
    const uint32_t* __restrict__ W2,
    float* __restrict__ Cf,
    uint32_t* __restrict__ H0, uint32_t* __restrict__ H1, uint32_t* __restrict__ H2,
    float q_scale, int round_half)
{
    extern __shared__ uint32_t sm[];
    const uint32_t* W;
    uint32_t* Ch;
    if (blockIdx.z == 0)      { W = W0; Ch = H0; }
    else if (blockIdx.z == 1) { W = W1; Ch = H1; }
    else                      { W = W2; Ch = H2; }
    const float scale = (blockIdx.z == 0) ? q_scale : 1.0f;

    const int tid = threadIdx.x;
    const int w = tid >> 5, l = tid & 31;
    const int g = l >> 2, t = l & 3;
    const int bm = blockIdx.y * 128;
    const int bn = blockIdx.x * 128;
    const int wm = (w & 1) * 64;
    const int wn = (w >> 1) * 64;

    const uint32_t* Abase = A + (size_t)bm * DW;
    const uint32_t* Wbase = W + (size_t)bn * DW;
    const uint32_t smb = smem_u32(sm);

    const int fr = tid >> 1;
    const int fc = (tid & 1) * 4;

    auto FILL = [&](int chunk, int st) {
        uint32_t ab = smb + st * (BUFW * 4);
        uint32_t bb = ab + TILEW * 4;
#pragma unroll
        for (int i = 0; i < 4; i++) {
            int c4 = (fc + i) * 4;
#pragma unroll
            for (int rh = 0; rh < 2; rh++) {
                int row = fr + rh * 64;
                uint32_t doff = (uint32_t)(row * LDAW + c4) * 4;
                size_t soff = (size_t)row * DW + chunk * 32 + c4;
                cp_async16(ab + doff, Abase + soff);
                cp_async16(bb + doff, Wbase + soff);
            }
        }
    };

    float acc[4][8][4];
#pragma unroll
    for (int i = 0; i < 4; i++)
#pragma unroll
        for (int j = 0; j < 8; j++)
#pragma unroll
            for (int q = 0; q < 4; q++) acc[i][j][q] = 0.f;

    FILL(0, 0); CP_COMMIT();

    const int NCH = D_MODEL / 64;
    for (int c = 0; c < NCH; c++) {
        CP_WAIT(0);
        __syncthreads();
        if (c + 1 < NCH) FILL(c + 1, (c + 1) & 1);
        CP_COMMIT();
        const int st = c & 1;
        const uint32_t* Ab = sm + st * BUFW;
        const uint32_t* Bb = Ab + TILEW;
#pragma unroll
        for (int s = 0; s < 4; s++) {
            uint32_t a[4][4];
#pragma unroll
            for (int i = 0; i < 4; i++) {
                const uint32_t* p = Ab + (wm + i * 16 + g) * LDAW + s * 8 + t;
                a[i][0] = p[0];
                a[i][1] = p[8 * LDAW];
                a[i][2] = p[4];
                a[i][3] = p[8 * LDAW + 4];
            }
#pragma unroll
            for (int j = 0; j < 8; j++) {
                const uint32_t* p = Bb + (wn + j * 8 + g) * LDAW + s * 8 + t;
                uint32_t b0 = p[0], b1 = p[4];
#pragma unroll
                for (int i = 0; i < 4; i++) mma16(acc[i][j], a[i], b0, b1);
            }
        }
        __syncthreads();
    }

#pragma unroll
    for (int i = 0; i < 4; i++) {
        int r0 = bm + wm + i * 16 + g;
#pragma unroll
        for (int j = 0; j < 8; j++) {
            float v0 = acc[i][j][0] * scale, v1 = acc[i][j][1] * scale;
            float v2 = acc[i][j][2] * scale, v3 = acc[i][j][3] * scale;
            if (round_half) {
                int wcol = ((bn + wn + j * 8) >> 1) + t;
                Ch[(size_t)r0 * DW + wcol] = packh2(v0, v1);
                Ch[(size_t)(r0 + 8) * DW + wcol] = packh2(v2, v3);
            } else {
                int col = bn + wn + j * 8 + 2 * t;
                *(float2*)(Cf + (size_t)r0 * D_MODEL + col) = make_float2(v0, v1);
                *(float2*)(Cf + (size_t)(r0 + 8) * D_MODEL + col) = make_float2(v2, v3);
            }
        }
    }
}

// ---------------------------------------------------------------------------
// Fused causal attention v6: fp16 mma + log2-domain softmax.
// Q pre-scaled by 0.125*log2e -> scores in log2 units; p = 2^(s-m) computed
// by ex2.approx.f16x2 (2 exps / MUFU op) whose packed output IS the PV
// A-fragment -> P never touches smem. alpha = ex2.f32(m_old-m_new).
// CTA = (b, h, 64 q rows), 128 thr / 4 warps; K double-buffered (cp.async);
// V single-buffered register-held transposed prefetch.
// ---------------------------------------------------------------------------
#define APW 36
#define ATTN_SMEM ((64+128+64)*APW*4)   // Q-stage + K[2] + Vt = 36864 bytes

__global__ __launch_bounds__(128, 3) void attn_fp16()
{
    extern __shared__ uint32_t sm[];
    uint32_t* Ps = sm;                 // [64][APW] Q staging only
    uint32_t* Kb = sm + 64 * APW;      // [2][64][APW]
    uint32_t* Vt = sm + 192 * APW;     // [64][APW] transposed [dd][n-pairs]

    const int tid = threadIdx.x;
    const int w = tid >> 5, l = tid & 31;
    const int g = l >> 2, t = l & 3;
    const int qt = blockIdx.x, h = blockIdx.y, b = blockIdx.z;

    const size_t base = (size_t)b * SEQ * DW + (size_t)h * (DK / 2);
    const uint32_t* qg = g_q + base + (size_t)qt * 64 * DW;
    const uint32_t* kg = g_k + base;
    const uint32_t* vg = g_v + base;
    const uint32_t smb = smem_u32(sm);
    const uint32_t Kb_b = smb + (uint32_t)64 * APW * 4;

    const int fr = tid >> 1;
    const int fc = (tid & 1) * 4;

    // Stage Q into Ps
#pragma unroll
    for (int i = 0; i < 4; i++) {
        int c4 = (fc + i) * 4;
        cp_async16(smb + (uint32_t)(fr * APW + c4) * 4, qg + (size_t)fr * DW + c4);
    }
    CP_COMMIT();
    // K(0) -> buffer 0
#pragma unroll
    for (int i = 0; i < 4; i++) {
        int c4 = (fc + i) * 4;
        cp_async16(Kb_b + (uint32_t)(fr * APW + c4) * 4, kg + (size_t)fr * DW + c4);
    }
    CP_COMMIT();
    CP_WAIT(1);
    __syncthreads();

    // Q fragments -> registers
    const int rowA = w * 16 + g, rowB = rowA + 8;
    uint32_t qf[4][4];
#pragma unroll
    for (int s = 0; s < 4; s++) {
        const uint32_t* pa = Ps + rowA * APW + s * 8 + t;
        const uint32_t* pb = Ps + rowB * APW + s * 8 + t;
        qf[s][0] = pa[0]; qf[s][1] = pb[0];
        qf[s][2] = pa[4]; qf[s][3] = pb[4];
    }

    // V(0) transpose -> Vt
    const int np = l;
    {
        const uint32_t* vr0 = vg + (size_t)(2 * np) * DW + w * 8;
        uint4 a0 = *(const uint4*)vr0;
        uint4 a1 = *(const uint4*)(vr0 + 4);
        uint4 b0 = *(const uint4*)(vr0 + DW);
        uint4 b1 = *(const uint4*)(vr0 + DW + 4);
        uint32_t av[8] = {a0.x, a0.y, a0.z, a0.w, a1.x, a1.y, a1.z, a1.w};
        uint32_t bv[8] = {b0.x, b0.y, b0.z, b0.w, b1.x, b1.y, b1.z, b1.w};
#pragma unroll
        for (int w8 = 0; w8 < 8; w8++) {
            int dd = w * 16 + 2 * w8;
            Vt[dd * APW + np]       = __byte_perm(av[w8], bv[w8], 0x5410);
            Vt[(dd + 1) * APW + np] = __byte_perm(av[w8], bv[w8], 0x7632);
        }
    }

    float mr2[2] = {-1e30f, -1e30f};
    float lr2[2] = {0.f, 0.f};
    float acco[8][4];
#pragma unroll
    for (int j = 0; j < 8; j++)
#pragma unroll
        for (int q = 0; q < 4; q++) acco[j][q] = 0.f;

    const int KT = qt;
    for (int kt = 0; kt <= KT; kt++) {
        const int cur = kt & 1, nxt = cur ^ 1;
        const bool more = (kt < KT);
        uint32_t av[8], bv[8];
        if (more) {
            const uint32_t* kg_t = kg + (size_t)(kt + 1) * 64 * DW;
#pragma unroll
            for (int i = 0; i < 4; i++) {
                int c4 = (fc + i) * 4;
                cp_async16(Kb_b + (uint32_t)(nxt * 64 * APW + fr * APW + c4) * 4,
                           kg_t + (size_t)fr * DW + c4);
            }
            const uint32_t* vp = vg + (size_t)(kt + 1) * 64 * DW +
                                 (size_t)(2 * np) * DW + w * 8;
            uint4 x0 = *(const uint4*)vp;
            uint4 x1 = *(const uint4*)(vp + 4);
            uint4 y0 = *(const uint4*)(vp + DW);
            uint4 y1 = *(const uint4*)(vp + DW + 4);
            av[0] = x0.x; av[1] = x0.y; av[2] = x0.z; av[3] = x0.w;
            av[4] = x1.x; av[5] = x1.y; av[6] = x1.z; av[7] = x1.w;
            bv[0] = y0.x; bv[1] = y0.y; bv[2] = y0.z; bv[3] = y0.w;
            bv[4] = y1.x; bv[5] = y1.y; bv[6] = y1.z; bv[7] = y1.w;
        }
        CP_COMMIT();
        CP_WAIT(1);
        __syncthreads();

        // ---- S = Q K^T (scores in log2 units) ----
        const uint32_t* kfb = Kb + cur * 64 * APW + g * APW + t;
        float accs[8][4];
#pragma unroll
        for (int j = 0; j < 8; j++)
#pragma unroll
            for (int q = 0; q < 4; q++) accs[j][q] = 0.f;
#pragma unroll
        for (int s = 0; s < 4; s++) {
#pragma unroll
            for (int j = 0; j < 8; j++) {
                const uint32_t* bp = kfb + (j * 8) * APW + s * 8;
                mma16(accs[j], qf[s], bp[0], bp[4]);
            }
        }

        // ---- causal mask (diagonal tile only) ----
        if (kt == KT) {
#pragma unroll
            for (int j = 0; j < 8; j++) {
                int c0 = j * 8 + 2 * t;
                if (c0 > rowA)     accs[j][0] = -1e30f;
                if (c0 + 1 > rowA) accs[j][1] = -1e30f;
                if (c0 > rowB)     accs[j][2] = -1e30f;
                if (c0 + 1 > rowB) accs[j][3] = -1e30f;
            }
        }

        // ---- online softmax in log2 domain ----
        float mxA = -1e30f, mxB = -1e30f;
#pragma unroll
        for (int j = 0; j < 8; j++) {
            mxA = fmaxf(mxA, fmaxf(accs[j][0], accs[j][1]));
            mxB = fmaxf(mxB, fmaxf(accs[j][2], accs[j][3]));
        }
        mxA = fmaxf(mxA, __shfl_xor_sync(0xffffffffu, mxA, 1));
        mxA = fmaxf(mxA, __shfl_xor_sync(0xffffffffu, mxA, 2));
        mxB = fmaxf(mxB, __shfl_xor_sync(0xffffffffu, mxB, 1));
        mxB = fmaxf(mxB, __shfl_xor_sync(0xffffffffu, mxB, 2));

        float mnA = fmaxf(mr2[0], mxA), mnB = fmaxf(mr2[1], mxB);
        float alA = ex2f(mr2[0] - mnA), alB = ex2f(mr2[1] - mnB);
        mr2[0] = mnA; mr2[1] = mnB;

        // p = 2^(s-m) via f16x2 ex2; packed outputs ARE the PV A-fragments
        uint32_t ph[8], qh[8];
#pragma unroll
        for (int j = 0; j < 8; j++) {
            ph[j] = h2ex2(packh2(accs[j][0] - mnA, accs[j][1] - mnA));
            qh[j] = h2ex2(packh2(accs[j][2] - mnB, accs[j][3] - mnB));
        }
        float sA = 0.f, sB = 0.f;
#pragma unroll
        for (int j = 0; j < 8; j++) {
            float2 fa = __half22float2(*(const __half2*)&ph[j]);
            float2 fb = __half22float2(*(const __half2*)&qh[j]);
            sA += fa.x + fa.y;
            sB += fb.x + fb.y;
        }
        sA += __shfl_xor_sync(0xffffffffu, sA, 1);
        sA += __shfl_xor_sync(0xffffffffu, sA, 2);
        sB += __shfl_xor_sync(0xffffffffu, sB, 1);
        sB += __shfl_xor_sync(0xffffffffu, sB, 2);
        lr2[0] = lr2[0] * alA + sA;
        lr2[1] = lr2[1] * alB + sB;

#pragma unroll
        for (int j = 0; j < 8; j++) {
            acco[j][0] *= alA; acco[j][1] *= alA;
            acco[j][2] *= alB; acco[j][3] *= alB;
        }

        // ---- O += P V straight from registers ----
        const uint32_t* vfb = Vt + g * APW + t;
#pragma unroll
        for (int s = 0; s < 4; s++) {
            uint32_t a[4] = {ph[2 * s], qh[2 * s], ph[2 * s + 1], qh[2 * s + 1]};
#pragma unroll
            for (int j = 0; j < 8; j++) {
                const uint32_t* bp = vfb + (j * 8) * APW + s * 8;
                mma16(acco[j], a, bp[0], bp[4]);
            }
        }

        if (more) {
            __syncthreads();   // all warps done reading V(kt)
#pragma unroll
            for (int w8 = 0; w8 < 8; w8++) {
                int dd = w * 16 + 2 * w8;
                Vt[dd * APW + np]       = __byte_perm(av[w8], bv[w8], 0x5410);
                Vt[(dd + 1) * APW + np] = __byte_perm(av[w8], bv[w8], 0x7632);
            }
        }
    }

    // Epilogue: normalize, write ctx as packed half2
    float invA = 1.f / lr2[0], invB = 1.f / lr2[1];
    uint32_t* og = g_ctx + base;
    size_t rA = (size_t)(qt * 64 + rowA) * DW;
    size_t rB = (size_t)(qt * 64 + rowB) * DW;
#pragma unroll
    for (int j = 0; j < 8; j++) {
        og[rA + j * 4 + t] = packh2(acco[j][0] * invA, acco[j][1] * invA);
        og[rB + j * 4 + t] = packh2(acco[j][2] * invB, acco[j][3] * invB);
    }
}

// ---------------------------------------------------------------------------
// Launch
// ---------------------------------------------------------------------------
extern "C" void kernel_launch(void* const* d_in, const int* in_sizes, int n_in,
                              void* d_out, int out_size)
{
    (void)in_sizes; (void)n_in; (void)out_size;
    const float* x  = (const float*)d_in[0];
    const float* Wq = (const float*)d_in[1];
    const float* Wk = (const float*)d_in[2];
    const float* Wv = (const float*)d_in[3];
    const float* Wo = (const float*)d_in[4];
    float* out = (float*)d_out;

    uint32_t *qp, *kp, *vp, *cp, *xh, *wh;
    cudaGetSymbolAddress((void**)&qp, g_q);
    cudaGetSymbolAddress((void**)&kp, g_k);
    cudaGetSymbolAddress((void**)&vp, g_v);
    cudaGetSymbolAddress((void**)&cp, g_ctx);
    cudaGetSymbolAddress((void**)&xh, g_xh);
    cudaGetSymbolAddress((void**)&wh, g_wh);

    cudaFuncSetAttribute(gemm_fp16, cudaFuncAttributeMaxDynamicSharedMemorySize,
                         GEMM_SMEM);
    cudaFuncSetAttribute(attn_fp16, cudaFuncAttributeMaxDynamicSharedMemorySize,
                         ATTN_SMEM);

    const int NX8 = ROWS * D_MODEL / 8;
    const int NW8 = D_MODEL * D_MODEL / 8;
    const size_t WSZW = (size_t)D_MODEL * DW;
    pre_half_x<<<(NX8 + 255) / 256, 256>>>((const float4*)x, (uint4*)xh, NX8);
    dim3 gw((NW8 + 255) / 256, 4);
    pre_half_w4<<<gw, 256>>>((const float4*)Wq, (const float4*)Wk,
                             (const float4*)Wv, (const float4*)Wo,
                             (uint4*)wh, NW8);

    // QKV projections; Q pre-scaled by log2e/sqrt(dk) -> log2-domain scores.
    const float QSCALE = 0.125f * 1.4426950408889634f;
    dim3 gproj(D_MODEL / 128, ROWS / 128, 3);
    gemm_fp16<<<gproj, 128, GEMM_SMEM>>>(xh, wh, wh + WSZW, wh + 2 * WSZW,
                                         nullptr, qp, kp, vp, QSCALE, 1);

    // Causal attention (fp16 mma, f16x2 ex2 softmax)
    dim3 gattn(SEQ / 64, NHEAD, BATCH);
    attn_fp16<<<gattn, 128, ATTN_SMEM>>>();

    // Output projection (fp32 output)
    dim3 gout(D_MODEL / 128, ROWS / 128, 1);
    gemm_fp16<<<gout, 128, GEMM_SMEM>>>(cp, wh + 3 * WSZW, wh + 3 * WSZW,
                                        wh + 3 * WSZW,
                                        out, nullptr, nullptr, nullptr, 1.0f, 0);
}

// round 17
// speedup vs baseline: 1.5732x; 1.1181x over previous
#include <cuda_runtime.h>
#include <cuda_fp16.h>
#include <cstdint>

#define D_MODEL 1024
#define NHEAD 16
#define DK 64
#define BATCH 4
#define SEQ 2048
#define ROWS (BATCH*SEQ)   // 8192
#define DW (D_MODEL/2)     // 512 words (half2) per row

// Scratch (no allocations allowed). q/k/v/ctx/x/W stored as packed half2 words.
__device__ uint32_t g_q[(size_t)ROWS * DW];
__device__ uint32_t g_k[(size_t)ROWS * DW];
__device__ uint32_t g_v[(size_t)ROWS * DW];
__device__ uint32_t g_ctx[(size_t)ROWS * DW];
__device__ uint32_t g_xh[(size_t)ROWS * DW];
__device__ uint32_t g_wh[(size_t)4 * D_MODEL * DW];

// ---------------------------------------------------------------------------
// Base-ISA helpers (sm_80 class only — NO tcgen05 on this toolchain target)
// ---------------------------------------------------------------------------
__device__ __forceinline__ uint32_t smem_u32(const void* p) {
    uint32_t a;
    asm("{ .reg .u64 t; cvta.to.shared.u64 t, %1; cvt.u32.u64 %0, t; }"
        : "=r"(a) : "l"(p));
    return a;
}
__device__ __forceinline__ uint32_t packh2(float a, float b) {
    __half2 h = __floats2half2_rn(a, b);
    return *(uint32_t*)&h;
}
__device__ __forceinline__ uint32_t h2ex2(uint32_t x) {
    uint32_t y;
    asm("ex2.approx.f16x2 %0, %1;" : "=r"(y) : "r"(x));
    return y;
}
__device__ __forceinline__ float ex2f(float x) {
    float y;
    asm("ex2.approx.f32 %0, %1;" : "=f"(y) : "f"(x));
    return y;
}
__device__ __forceinline__ void mma16(float* c, const uint32_t* a,
                                      uint32_t b0, uint32_t b1) {
    asm volatile(
        "mma.sync.aligned.m16n8k16.row.col.f32.f16.f16.f32 "
        "{%0,%1,%2,%3}, {%4,%5,%6,%7}, {%8,%9}, {%0,%1,%2,%3};"
        : "+f"(c[0]), "+f"(c[1]), "+f"(c[2]), "+f"(c[3])
        : "r"(a[0]), "r"(a[1]), "r"(a[2]), "r"(a[3]), "r"(b0), "r"(b1));
}
#define LDSM4(r0, r1, r2, r3, a) \
    asm volatile("ldmatrix.sync.aligned.m8n8.x4.shared.b16 {%0,%1,%2,%3}, [%4];" \
                 : "=r"(r0), "=r"(r1), "=r"(r2), "=r"(r3) : "r"(a))
#define LDSM4T(r0, r1, r2, r3, a) \
    asm volatile("ldmatrix.sync.aligned.m8n8.x4.trans.shared.b16 {%0,%1,%2,%3}, [%4];" \
                 : "=r"(r0), "=r"(r1), "=r"(r2), "=r"(r3) : "r"(a))
__device__ __forceinline__ void cp_async16(uint32_t dst, const void* src) {
    asm volatile("cp.async.cg.shared.global [%0], [%1], 16;"
                 :: "r"(dst), "l"(src));
}
#define CP_COMMIT() asm volatile("cp.async.commit_group;" ::: "memory")
#define CP_WAIT(n)  asm volatile("cp.async.wait_group %0;" :: "n"(n) : "memory")

// ---------------------------------------------------------------------------
// Pre-convert fp32 -> packed fp16 (rn).
// ---------------------------------------------------------------------------
__global__ void pre_half_x(const float4* __restrict__ s, uint4* __restrict__ d,
                           int n8) {
    int i = blockIdx.x * blockDim.x + threadIdx.x;
    if (i < n8) {
        float4 v0 = s[2 * i], v1 = s[2 * i + 1];
        d[i] = make_uint4(packh2(v0.x, v0.y), packh2(v0.z, v0.w),
                          packh2(v1.x, v1.y), packh2(v1.z, v1.w));
    }
}
__global__ void pre_half_w4(const float4* __restrict__ w0, const float4* __restrict__ w1,
                            const float4* __restrict__ w2, const float4* __restrict__ w3,
                            uint4* __restrict__ d, int n8) {
    int i = blockIdx.x * blockDim.x + threadIdx.x;
    if (i >= n8) return;
    const float4* s = (blockIdx.y == 0) ? w0 : (blockIdx.y == 1) ? w1
                    : (blockIdx.y == 2) ? w2 : w3;
    float4 v0 = s[2 * i], v1 = s[2 * i + 1];
    d[(size_t)blockIdx.y * n8 + i] =
        make_uint4(packh2(v0.x, v0.y), packh2(v0.z, v0.w),
                   packh2(v1.x, v1.y), packh2(v1.z, v1.w));
}

// ---------------------------------------------------------------------------
// FP16 GEMM (unchanged from round 15/16)
// ---------------------------------------------------------------------------
#define LDAW 36
#define TILEW (128*LDAW)
#define BUFW  (2*TILEW)
#define NST 2
#define GEMM_SMEM (NST*BUFW*4)  // 73728 bytes

__global__ __launch_bounds__(128, 3) void gemm_fp16(
    const uint32_t* __restrict__ A,
    const uint32_t* __restrict__ W0, const uint32_t* __restrict__ W1,
    const uint32_t* __restrict__ W2,
    float* __restrict__ Cf,
    uint32_t* __restrict__ H0, uint32_t* __restrict__ H1, uint32_t* __restrict__ H2,
    float q_scale, int round_half)
{
    extern __shared__ uint32_t sm[];
    const uint32_t* W;
    uint32_t* Ch;
    if (blockIdx.z == 0)      { W = W0; Ch = H0; }
    else if (blockIdx.z == 1) { W = W1; Ch = H1; }
    else                      { W = W2; Ch = H2; }
    const float scale = (blockIdx.z == 0) ? q_scale : 1.0f;

    const int tid = threadIdx.x;
    const int w = tid >> 5, l = tid & 31;
    const int g = l >> 2, t = l & 3;
    const int bm = blockIdx.y * 128;
    const int bn = blockIdx.x * 128;
    const int wm = (w & 1) * 64;
    const int wn = (w >> 1) * 64;

    const uint32_t* Abase = A + (size_t)bm * DW;
    const uint32_t* Wbase = W + (size_t)bn * DW;
    const uint32_t smb = smem_u32(sm);

    const int fr = tid >> 1;
    const int fc = (tid & 1) * 4;

    auto FILL = [&](int chunk, int st) {
        uint32_t ab = smb + st * (BUFW * 4);
        uint32_t bb = ab + TILEW * 4;
#pragma unroll
        for (int i = 0; i < 4; i++) {
            int c4 = (fc + i) * 4;
#pragma unroll
            for (int rh = 0; rh < 2; rh++) {
                int row = fr + rh * 64;
                uint32_t doff = (uint32_t)(row * LDAW + c4) * 4;
                size_t soff = (size_t)row * DW + chunk * 32 + c4;
                cp_async16(ab + doff, Abase + soff);
                cp_async16(bb + doff, Wbase + soff);
            }
        }
    };

    float acc[4][8][4];
#pragma unroll
    for (int i = 0; i < 4; i++)
#pragma unroll
        for (int j = 0; j < 8; j++)
#pragma unroll
            for (int q = 0; q < 4; q++) acc[i][j][q] = 0.f;

    FILL(0, 0); CP_COMMIT();

    const int NCH = D_MODEL / 64;
    for (int c = 0; c < NCH; c++) {
        CP_WAIT(0);
        __syncthreads();
        if (c + 1 < NCH) FILL(c + 1, (c + 1) & 1);
        CP_COMMIT();
        const int st = c & 1;
        const uint32_t* Ab = sm + st * BUFW;
        const uint32_t* Bb = Ab + TILEW;
#pragma unroll
        for (int s = 0; s < 4; s++) {
            uint32_t a[4][4];
#pragma unroll
            for (int i = 0; i < 4; i++) {
                const uint32_t* p = Ab + (wm + i * 16 + g) * LDAW + s * 8 + t;
                a[i][0] = p[0];
                a[i][1] = p[8 * LDAW];
                a[i][2] = p[4];
                a[i][3] = p[8 * LDAW + 4];
            }
#pragma unroll
            for (int j = 0; j < 8; j++) {
                const uint32_t* p = Bb + (wn + j * 8 + g) * LDAW + s * 8 + t;
                uint32_t b0 = p[0], b1 = p[4];
#pragma unroll
                for (int i = 0; i < 4; i++) mma16(acc[i][j], a[i], b0, b1);
            }
        }
        __syncthreads();
    }

#pragma unroll
    for (int i = 0; i < 4; i++) {
        int r0 = bm + wm + i * 16 + g;
#pragma unroll
        for (int j = 0; j < 8; j++) {
            float v0 = acc[i][j][0] * scale, v1 = acc[i][j][1] * scale;
            float v2 = acc[i][j][2] * scale, v3 = acc[i][j][3] * scale;
            if (round_half) {
                int wcol = ((bn + wn + j * 8) >> 1) + t;
                Ch[(size_t)r0 * DW + wcol] = packh2(v0, v1);
                Ch[(size_t)(r0 + 8) * DW + wcol] = packh2(v2, v3);
            } else {
                int col = bn + wn + j * 8 + 2 * t;
                *(float2*)(Cf + (size_t)r0 * D_MODEL + col) = make_float2(v0, v1);
                *(float2*)(Cf + (size_t)(r0 + 8) * D_MODEL + col) = make_float2(v2, v3);
            }
        }
    }
}

// ---------------------------------------------------------------------------
// Fused causal attention v7: fp16 mma + log2 softmax + ldmatrix fragments.
// K and V cp.async double-buffered in NATURAL [seq][dd] layout; K fragments
// via ldmatrix.x4, V fragments via ldmatrix.x4.trans (no manual transpose).
// 128 thr / 4 warps, 4 CTAs/SM. Race-free: prefetch issued after the barrier
// that retires all readers of the buffer it overwrites.
// ---------------------------------------------------------------------------
#define APW 36
#define ATTN_SMEM ((64+128+128)*APW*4)   // Q + K[2] + V[2] = 46080 bytes

__global__ __launch_bounds__(128, 4) void attn_fp16()
{
    extern __shared__ uint32_t sm[];
    uint32_t* Ps = sm;                 // [64][APW] Q staging
    // K: sm + 64*APW, V: sm + 192*APW

    const int tid = threadIdx.x;
    const int w = tid >> 5, l = tid & 31;
    const int g = l >> 2, t = l & 3;
    const int qt = blockIdx.x, h = blockIdx.y, b = blockIdx.z;

    const size_t base = (size_t)b * SEQ * DW + (size_t)h * (DK / 2);
    const uint32_t* qg = g_q + base + (size_t)qt * 64 * DW;
    const uint32_t* kg = g_k + base;
    const uint32_t* vg = g_v + base;
    const uint32_t smb = smem_u32(sm);
    const uint32_t Kb_b = smb + (uint32_t)64 * APW * 4;
    const uint32_t Vb_b = smb + (uint32_t)192 * APW * 4;

    const int fr = tid >> 1;
    const int fc = (tid & 1) * 4;

    // ldmatrix per-lane offsets (bytes)
    const int lr8 = l & 7;
    const uint32_t k_lane = (uint32_t)((((l >> 4) * 8 + lr8) * APW +
                                        ((l >> 3) & 1) * 4)) * 4;
    const uint32_t v_lane = (uint32_t)(((((l >> 3) & 1) * 8 + lr8) * APW +
                                        (l >> 4) * 4)) * 4;

    // Stage Q (group 0)
#pragma unroll
    for (int i = 0; i < 4; i++) {
        int c4 = (fc + i) * 4;
        cp_async16(smb + (uint32_t)(fr * APW + c4) * 4, qg + (size_t)fr * DW + c4);
    }
    CP_COMMIT();
    // K(0), V(0) -> buffer 0 (group 1)
#pragma unroll
    for (int i = 0; i < 4; i++) {
        int c4 = (fc + i) * 4;
        cp_async16(Kb_b + (uint32_t)(fr * APW + c4) * 4, kg + (size_t)fr * DW + c4);
        cp_async16(Vb_b + (uint32_t)(fr * APW + c4) * 4, vg + (size_t)fr * DW + c4);
    }
    CP_COMMIT();
    CP_WAIT(1);          // Q landed
    __syncthreads();

    // Q fragments -> registers
    const int rowA = w * 16 + g, rowB = rowA + 8;
    uint32_t qf[4][4];
#pragma unroll
    for (int s = 0; s < 4; s++) {
        const uint32_t* pa = Ps + rowA * APW + s * 8 + t;
        const uint32_t* pb = Ps + rowB * APW + s * 8 + t;
        qf[s][0] = pa[0]; qf[s][1] = pb[0];
        qf[s][2] = pa[4]; qf[s][3] = pb[4];
    }

    float mr2[2] = {-1e30f, -1e30f};
    float lr2[2] = {0.f, 0.f};
    float acco[8][4];
#pragma unroll
    for (int j = 0; j < 8; j++)
#pragma unroll
        for (int q = 0; q < 4; q++) acco[j][q] = 0.f;

    const int KT = qt;
    for (int kt = 0; kt <= KT; kt++) {
        const int cur = kt & 1;
        CP_WAIT(0);          // K/V(kt) complete (this thread)
        __syncthreads();     // ...globally; all warps done with buffer nxt

        // Prefetch K/V(kt+1) into the other buffer (safe post-barrier)
        if (kt < KT) {
            const uint32_t boff = (uint32_t)((kt + 1) & 1) * 64 * APW * 4;
            const uint32_t* kg_t = kg + (size_t)(kt + 1) * 64 * DW;
            const uint32_t* vg_t = vg + (size_t)(kt + 1) * 64 * DW;
#pragma unroll
            for (int i = 0; i < 4; i++) {
                int c4 = (fc + i) * 4;
                uint32_t doff = (uint32_t)(fr * APW + c4) * 4;
                cp_async16(Kb_b + boff + doff, kg_t + (size_t)fr * DW + c4);
                cp_async16(Vb_b + boff + doff, vg_t + (size_t)fr * DW + c4);
            }
        }
        CP_COMMIT();

        // ---- S = Q K^T : 16x64 per warp (K frags via ldmatrix) ----
        const uint32_t kbase = Kb_b + (uint32_t)cur * 64 * APW * 4 + k_lane;
        float accs[8][4];
#pragma unroll
        for (int j = 0; j < 8; j++)
#pragma unroll
            for (int q = 0; q < 4; q++) accs[j][q] = 0.f;
#pragma unroll
        for (int s = 0; s < 4; s++) {
            uint32_t ka = kbase + s * 32;
#pragma unroll
            for (int jp = 0; jp < 8; jp += 2) {
                uint32_t r0, r1, r2, r3;
                LDSM4(r0, r1, r2, r3, ka + (uint32_t)jp * 8 * APW * 4);
                mma16(accs[jp], qf[s], r0, r1);
                mma16(accs[jp + 1], qf[s], r2, r3);
            }
        }

        // ---- causal mask (diagonal tile only) ----
        if (kt == KT) {
#pragma unroll
            for (int j = 0; j < 8; j++) {
                int c0 = j * 8 + 2 * t;
                if (c0 > rowA)     accs[j][0] = -1e30f;
                if (c0 + 1 > rowA) accs[j][1] = -1e30f;
                if (c0 > rowB)     accs[j][2] = -1e30f;
                if (c0 + 1 > rowB) accs[j][3] = -1e30f;
            }
        }

        // ---- online softmax in log2 domain ----
        float mxA = -1e30f, mxB = -1e30f;
#pragma unroll
        for (int j = 0; j < 8; j++) {
            mxA = fmaxf(mxA, fmaxf(accs[j][0], accs[j][1]));
            mxB = fmaxf(mxB, fmaxf(accs[j][2], accs[j][3]));
        }
        mxA = fmaxf(mxA, __shfl_xor_sync(0xffffffffu, mxA, 1));
        mxA = fmaxf(mxA, __shfl_xor_sync(0xffffffffu, mxA, 2));
        mxB = fmaxf(mxB, __shfl_xor_sync(0xffffffffu, mxB, 1));
        mxB = fmaxf(mxB, __shfl_xor_sync(0xffffffffu, mxB, 2));

        float mnA = fmaxf(mr2[0], mxA), mnB = fmaxf(mr2[1], mxB);
        float alA = ex2f(mr2[0] - mnA), alB = ex2f(mr2[1] - mnB);
        mr2[0] = mnA; mr2[1] = mnB;

        uint32_t ph[8], qh[8];
#pragma unroll
        for (int j = 0; j < 8; j++) {
            ph[j] = h2ex2(packh2(accs[j][0] - mnA, accs[j][1] - mnA));
            qh[j] = h2ex2(packh2(accs[j][2] - mnB, accs[j][3] - mnB));
        }
        float sA = 0.f, sB = 0.f;
#pragma unroll
        for (int j = 0; j < 8; j++) {
            float2 fa = __half22float2(*(const __half2*)&ph[j]);
            float2 fb = __half22float2(*(const __half2*)&qh[j]);
            sA += fa.x + fa.y;
            sB += fb.x + fb.y;
        }
        sA += __shfl_xor_sync(0xffffffffu, sA, 1);
        sA += __shfl_xor_sync(0xffffffffu, sA, 2);
        sB += __shfl_xor_sync(0xffffffffu, sB, 1);
        sB += __shfl_xor_sync(0xffffffffu, sB, 2);
        lr2[0] = lr2[0] * alA + sA;
        lr2[1] = lr2[1] * alB + sB;

#pragma unroll
        for (int j = 0; j < 8; j++) {
            acco[j][0] *= alA; acco[j][1] *= alA;
            acco[j][2] *= alB; acco[j][3] *= alB;
        }

        // ---- O += P V (P from registers; V frags via ldmatrix.trans) ----
        const uint32_t vbase = Vb_b + (uint32_t)cur * 64 * APW * 4 + v_lane;
#pragma unroll
        for (int s = 0; s < 4; s++) {
            uint32_t a[4] = {ph[2 * s], qh[2 * s], ph[2 * s + 1], qh[2 * s + 1]};
            uint32_t va = vbase + (uint32_t)s * 16 * APW * 4;
#pragma unroll
            for (int jp = 0; jp < 8; jp += 2) {
                uint32_t r0, r1, r2, r3;
                LDSM4T(r0, r1, r2, r3, va + (uint32_t)jp * 16);
                mma16(acco[jp], a, r0, r1);
                mma16(acco[jp + 1], a, r2, r3);
            }
        }
    }

    // Epilogue: normalize, write ctx as packed half2
    float invA = 1.f / lr2[0], invB = 1.f / lr2[1];
    uint32_t* og = g_ctx + base;
    size_t rA = (size_t)(qt * 64 + rowA) * DW;
    size_t rB = (size_t)(qt * 64 + rowB) * DW;
#pragma unroll
    for (int j = 0; j < 8; j++) {
        og[rA + j * 4 + t] = packh2(acco[j][0] * invA, acco[j][1] * invA);
        og[rB + j * 4 + t] = packh2(acco[j][2] * invB, acco[j][3] * invB);
    }
}

// ---------------------------------------------------------------------------
// Launch
// ---------------------------------------------------------------------------
extern "C" void kernel_launch(void* const* d_in, const int* in_sizes, int n_in,
                              void* d_out, int out_size)
{
    (void)in_sizes; (void)n_in; (void)out_size;
    const float* x  = (const float*)d_in[0];
    const float* Wq = (const float*)d_in[1];
    const float* Wk = (const float*)d_in[2];
    const float* Wv = (const float*)d_in[3];
    const float* Wo = (const float*)d_in[4];
    float* out = (float*)d_out;

    uint32_t *qp, *kp, *vp, *cp, *xh, *wh;
    cudaGetSymbolAddress((void**)&qp, g_q);
    cudaGetSymbolAddress((void**)&kp, g_k);
    cudaGetSymbolAddress((void**)&vp, g_v);
    cudaGetSymbolAddress((void**)&cp, g_ctx);
    cudaGetSymbolAddress((void**)&xh, g_xh);
    cudaGetSymbolAddress((void**)&wh, g_wh);

    cudaFuncSetAttribute(gemm_fp16, cudaFuncAttributeMaxDynamicSharedMemorySize,
                         GEMM_SMEM);
    cudaFuncSetAttribute(attn_fp16, cudaFuncAttributeMaxDynamicSharedMemorySize,
                         ATTN_SMEM);

    const int NX8 = ROWS * D_MODEL / 8;
    const int NW8 = D_MODEL * D_MODEL / 8;
    const size_t WSZW = (size_t)D_MODEL * DW;
    pre_half_x<<<(NX8 + 255) / 256, 256>>>((const float4*)x, (uint4*)xh, NX8);
    dim3 gw((NW8 + 255) / 256, 4);
    pre_half_w4<<<gw, 256>>>((const float4*)Wq, (const float4*)Wk,
                             (const float4*)Wv, (const float4*)Wo,
                             (uint4*)wh, NW8);

    // QKV projections; Q pre-scaled by log2e/sqrt(dk) -> log2-domain scores.
    const float QSCALE = 0.125f * 1.4426950408889634f;
    dim3 gproj(D_MODEL / 128, ROWS / 128, 3);
    gemm_fp16<<<gproj, 128, GEMM_SMEM>>>(xh, wh, wh + WSZW, wh + 2 * WSZW,
                                         nullptr, qp, kp, vp, QSCALE, 1);

    // Causal attention (fp16 mma, ldmatrix fragments)
    dim3 gattn(SEQ / 64, NHEAD, BATCH);
    attn_fp16<<<gattn, 128, ATTN_SMEM>>>();

    // Output projection (fp32 output)
    dim3 gout(D_MODEL / 128, ROWS / 128, 1);
    gemm_fp16<<<gout, 128, GEMM_SMEM>>>(cp, wh + 3 * WSZW, wh + 3 * WSZW,
                                        wh + 3 * WSZW,
                                        out, nullptr, nullptr, nullptr, 1.0f, 0);
}